// round 11
// baseline (speedup 1.0000x reference)
#include <cuda_runtime.h>
#include <cuda_bf16.h>
#include <math.h>
#include <stdint.h>

#define BSZ   1024
#define NBIN  4
#define BSIN  128
#define NKEY  5
#define NBO   8
#define BSO   512
#define NHID  4096
#define DKQ   64
#define GATES 2048

// ------------- scratch (allocation-free: __device__ globals) -------------
__device__ float g_gates  [(size_t)BSZ * NBO * GATES];
__device__ float g_hnew   [(size_t)BSZ * NBO * BSO];
__device__ float g_q2     [(size_t)BSZ * NBO * DKQ];
__device__ float g_k2     [(size_t)BSZ * NBO * DKQ];
__device__ float g_v2     [(size_t)BSZ * NBO * DKQ];
__device__ float g_mblk   [(size_t)BSZ * NBO];
// bf16 hi/lo split operands for the tensor-core LSTM GEMM
__device__ __nv_bfloat16 g_ahi[(size_t)NBO * 1024 * 1024];
__device__ __nv_bfloat16 g_alo[(size_t)NBO * 1024 * 1024];
__device__ __nv_bfloat16 g_bhi[(size_t)NBO * 2048 * 1024];
__device__ __nv_bfloat16 g_blo[(size_t)NBO * 2048 * 1024];

__device__ __forceinline__ float sigf(float x) { return 1.0f / (1.0f + expf(-x)); }

// ------------- f32x2 packed FMA helpers -------------
__device__ __forceinline__ unsigned long long pk2(float x, float y) {
    unsigned long long r;
    asm("mov.b64 %0, {%1, %2};" : "=l"(r) : "f"(x), "f"(y));
    return r;
}
__device__ __forceinline__ void fma2(unsigned long long& d, unsigned long long a, unsigned long long b) {
    asm("fma.rn.f32x2 %0, %1, %2, %0;" : "+l"(d) : "l"(a), "l"(b));
}
__device__ __forceinline__ float2 upk2(unsigned long long v) {
    float2 f;
    asm("mov.b64 {%0, %1}, %2;" : "=f"(f.x), "=f"(f.y) : "l"(v));
    return f;
}

// ------------- mma.sync / ldmatrix / cp.async helpers -------------
__device__ __forceinline__ uint32_t smem_u32(const void* p) {
    uint32_t a;
    asm("{ .reg .u64 t; cvta.to.shared.u64 t, %1; cvt.u32.u64 %0, t; }" : "=r"(a) : "l"(p));
    return a;
}
__device__ __forceinline__ uint32_t swz64(uint32_t b) { return b ^ ((b >> 3) & 0x30); }

__device__ __forceinline__ void ldsm_x4(uint32_t addr, uint32_t* r) {
    asm volatile("ldmatrix.sync.aligned.m8n8.x4.shared.b16 {%0,%1,%2,%3}, [%4];"
                 : "=r"(r[0]), "=r"(r[1]), "=r"(r[2]), "=r"(r[3]) : "r"(addr));
}
__device__ __forceinline__ void mma_bf16(float* c, const uint32_t* a, uint32_t b0, uint32_t b1) {
    asm volatile("mma.sync.aligned.m16n8k16.row.col.f32.bf16.bf16.f32 "
                 "{%0,%1,%2,%3}, {%4,%5,%6,%7}, {%8,%9}, {%0,%1,%2,%3};"
                 : "+f"(c[0]), "+f"(c[1]), "+f"(c[2]), "+f"(c[3])
                 : "r"(a[0]), "r"(a[1]), "r"(a[2]), "r"(a[3]), "r"(b0), "r"(b1));
}
__device__ __forceinline__ void cpa16(uint32_t dst, const void* src) {
    asm volatile("cp.async.cg.shared.global [%0], [%1], 16;" :: "r"(dst), "l"(src));
}
__device__ __forceinline__ void cp_commit() { asm volatile("cp.async.commit_group;"); }
__device__ __forceinline__ void cp_wait1() { asm volatile("cp.async.wait_group 1;"); }
__device__ __forceinline__ void cp_wait0() { asm volatile("cp.async.wait_group 0;"); }

// =====================================================================
// K_PRE: fused (k1 input-attention | prep_b | prep_a2).
// =====================================================================
#define K1_BPB 4
#define K1_BLOCKS   (BSZ / K1_BPB)                /* 256  */
#define PB_BLOCKS   (32 * 16 * 8)                 /* 4096 */
#define PA_BLOCKS   2048
#define PRE_BLOCKS  (K1_BLOCKS + PB_BLOCKS + PA_BLOCKS)

struct K1Smem {
    float sx[K1_BPB][NKEY * BSIN];
    float sk[K1_BPB][NKEY][DKQ];
    float sv[K1_BPB][NKEY][DKQ];
    float sq[K1_BPB][NBO][DKQ];
    float so[K1_BPB][NBO][DKQ];
    float sattn[K1_BPB][NBO][NKEY];
    float smb[K1_BPB][NBO];
};
union PreSmem {
    K1Smem k1;
    float ts[64][65];
};

__global__ void __launch_bounds__(256) k_pre(
    const float* __restrict__ inp, const float* __restrict__ hx,
    const float* __restrict__ wq, const float* __restrict__ wk, const float* __restrict__ wv,
    const float* __restrict__ fcw, const float* __restrict__ fcb,
    const float* __restrict__ w_ih, const float* __restrict__ w_hh,
    float* __restrict__ mask_out)
{
    __shared__ PreSmem su;
    const int tid = threadIdx.x;
    const int bid = blockIdx.x;

    if (bid < K1_BLOCKS) {
        auto& sx = su.k1.sx;  auto& sk = su.k1.sk;  auto& sv = su.k1.sv;
        auto& sq = su.k1.sq;  auto& so = su.k1.so;
        auto& sattn = su.k1.sattn;  auto& smb = su.k1.smb;
        const int b0 = bid * K1_BPB;

        for (int i = tid; i < K1_BPB * NKEY * BSIN; i += 256) {
            int bi = i / (NKEY * BSIN);
            int j  = i % (NKEY * BSIN);
            sx[bi][j] = (j < NBIN * BSIN) ? inp[(size_t)(b0 + bi) * (NBIN * BSIN) + j] : 0.0f;
        }
        __syncthreads();

        if (tid < 128) {
            const int n  = tid >> 4;
            const int e4 = (tid & 15) * 4;
            const float* wp = wq + (size_t)(n * BSO) * DKQ + e4;
            float4 aq[K1_BPB];
#pragma unroll
            for (int bi = 0; bi < K1_BPB; bi++) aq[bi] = make_float4(0.f, 0.f, 0.f, 0.f);
#pragma unroll 4
            for (int d = 0; d < BSO; d++) {
                float4 w4 = *(const float4*)(wp + (size_t)d * DKQ);
#pragma unroll
                for (int bi = 0; bi < K1_BPB; bi++) {
                    float hv = __ldg(&hx[(size_t)(b0 + bi) * NHID + n * BSO + d]);
                    aq[bi].x += hv * w4.x; aq[bi].y += hv * w4.y;
                    aq[bi].z += hv * w4.z; aq[bi].w += hv * w4.w;
                }
            }
#pragma unroll
            for (int bi = 0; bi < K1_BPB; bi++) *(float4*)&sq[bi][n][e4] = aq[bi];
        } else if (tid < 128 + NKEY * 16) {
            const int g  = tid - 128;
            const int n  = g / 16;
            const int e4 = (g % 16) * 4;
            const float* wkp = wk + (size_t)(n * BSIN) * DKQ + e4;
            const float* wvp = wv + (size_t)(n * BSIN) * DKQ + e4;
            float4 ak[K1_BPB], av[K1_BPB];
#pragma unroll
            for (int bi = 0; bi < K1_BPB; bi++) {
                ak[bi] = make_float4(0.f, 0.f, 0.f, 0.f);
                av[bi] = make_float4(0.f, 0.f, 0.f, 0.f);
            }
#pragma unroll 4
            for (int d = 0; d < BSIN; d++) {
                float4 a4 = *(const float4*)(wkp + (size_t)d * DKQ);
                float4 b4 = *(const float4*)(wvp + (size_t)d * DKQ);
#pragma unroll
                for (int bi = 0; bi < K1_BPB; bi++) {
                    float xv = sx[bi][n * BSIN + d];
                    ak[bi].x += xv * a4.x; ak[bi].y += xv * a4.y;
                    ak[bi].z += xv * a4.z; ak[bi].w += xv * a4.w;
                    av[bi].x += xv * b4.x; av[bi].y += xv * b4.y;
                    av[bi].z += xv * b4.z; av[bi].w += xv * b4.w;
                }
            }
#pragma unroll
            for (int bi = 0; bi < K1_BPB; bi++) {
                *(float4*)&sk[bi][n][e4] = ak[bi];
                *(float4*)&sv[bi][n][e4] = av[bi];
            }
        }
        __syncthreads();

        if (tid < K1_BPB * NBO) {
            int bi = tid / NBO, n = tid % NBO;
            float s[NKEY];
            float mx = -1e30f;
            for (int j = 0; j < NKEY; j++) {
                float a = 0.f;
                for (int e = 0; e < DKQ; e++) a += sq[bi][n][e] * sk[bi][j][e];
                a *= 0.125f;
                s[j] = a;
                mx = fmaxf(mx, a);
            }
            float den = 0.f;
            for (int j = 0; j < NKEY; j++) { s[j] = expf(s[j] - mx); den += s[j]; }
            float inv = 1.0f / den;
            for (int j = 0; j < NKEY; j++) sattn[bi][n][j] = s[j] * inv;
        }
        __syncthreads();

        if (tid < K1_BPB) {
            int bi = tid;
            float sc[NBO], t[NBO];
            for (int n = 0; n < NBO; n++) { sc[n] = sattn[bi][n][0]; t[n] = sc[n]; }
            for (int a = 0; a < 4; a++) {
                int mi = a;
                for (int b = a + 1; b < NBO; b++) if (t[b] > t[mi]) mi = b;
                float tmp = t[a]; t[a] = t[mi]; t[mi] = tmp;
            }
            float thr = t[3] - 0.01f;
            for (int n = 0; n < NBO; n++) {
                float m = (sc[n] > thr) ? 1.0f : 0.0f;
                smb[bi][n] = m;
                g_mblk[(size_t)(b0 + bi) * NBO + n] = m;
            }
        }
        __syncthreads();

        for (int i = tid; i < K1_BPB * NBO * DKQ; i += 256) {
            int bi = i / (NBO * DKQ);
            int r  = i % (NBO * DKQ);
            int n  = r / DKQ;
            int e  = r % DKQ;
            float a = 0.f;
            for (int j = 0; j < NKEY; j++) a += sattn[bi][n][j] * sv[bi][j][e];
            so[bi][n][e] = a;
        }
        __syncthreads();

        for (int round = 0; round < 4; round++) {
            int g  = round * 256 + tid;
            int n  = g >> 7;
            int c4 = (g & 127) * 4;
            float4 bias = *(const float4*)&fcb[c4];
            float4 a[K1_BPB];
#pragma unroll
            for (int bi = 0; bi < K1_BPB; bi++) a[bi] = bias;
#pragma unroll 4
            for (int e = 0; e < DKQ; e++) {
                float4 w4 = *(const float4*)&fcw[(size_t)e * BSO + c4];
#pragma unroll
                for (int bi = 0; bi < K1_BPB; bi++) {
                    float s = so[bi][n][e];
                    a[bi].x += s * w4.x; a[bi].y += s * w4.y;
                    a[bi].z += s * w4.z; a[bi].w += s * w4.w;
                }
            }
#pragma unroll
            for (int bi = 0; bi < K1_BPB; bi++) {
                float xs[4] = {a[bi].x, a[bi].y, a[bi].z, a[bi].w};
                union { __nv_bfloat16 h[4]; uint2 u; } vh, vl;
#pragma unroll
                for (int j = 0; j < 4; j++) {
                    __nv_bfloat16 hi = __float2bfloat16(xs[j]);
                    vh.h[j] = hi;
                    vl.h[j] = __float2bfloat16(xs[j] - __bfloat162float(hi));
                }
                size_t ao = ((size_t)n * 1024 + (b0 + bi)) * 1024 + c4;
                *(uint2*)&g_ahi[ao] = vh.u;
                *(uint2*)&g_alo[ao] = vl.u;
                float m = smb[bi][n];
                *(float4*)&mask_out[(size_t)(b0 + bi) * NHID + n * BSO + c4] = make_float4(m, m, m, m);
            }
        }
    } else if (bid < K1_BLOCKS + PB_BLOCKS) {
        auto& ts = su.ts;
        const int pb = bid - K1_BLOCKS;
        const int n0 = (pb & 31) * 64;
        const int k0 = ((pb >> 5) & 15) * 64;
        const int kb = pb >> 9;

        const float* srcm = (k0 < 512) ? (w_ih + (size_t)kb * 512 * GATES)
                                       : (w_hh + (size_t)kb * 512 * GATES);
        const int krow0 = (k0 < 512) ? k0 : (k0 - 512);

#pragma unroll
        for (int p = 0; p < 16; p++) {
            int idx = p * 256 + tid;
            int r = idx >> 6;
            int c = idx & 63;
            ts[r][c] = srcm[(size_t)(krow0 + r) * GATES + n0 + c];
        }
        __syncthreads();

#pragma unroll
        for (int g = 0; g < 2; g++) {
            int n   = (tid >> 3) + g * 32;
            int kk0 = (tid & 7) * 8;
            union { __nv_bfloat16 h[8]; uint4 u; } vh, vl;
#pragma unroll
            for (int j = 0; j < 8; j++) {
                float x = ts[kk0 + j][n];
                __nv_bfloat16 hi = __float2bfloat16(x);
                vh.h[j] = hi;
                vl.h[j] = __float2bfloat16(x - __bfloat162float(hi));
            }
            size_t o = ((size_t)kb * GATES + n0 + n) * 1024 + k0 + kk0;
            *(uint4*)&g_bhi[o] = vh.u;
            *(uint4*)&g_blo[o] = vl.u;
        }
    } else {
        size_t idx = (size_t)(bid - K1_BLOCKS - PB_BLOCKS) * 256 + tid;
        int k8 = (int)(idx & 63);
        int m  = (int)((idx >> 6) & 1023);
        int kb = (int)(idx >> 16);
        int k  = k8 * 8;

        const float* src = &hx[(size_t)m * NHID + kb * BSO + k];
        float4 a = *(const float4*)src;
        float4 b = *(const float4*)(src + 4);
        float xs[8] = {a.x, a.y, a.z, a.w, b.x, b.y, b.z, b.w};
        union { __nv_bfloat16 h[8]; uint4 u; } vh, vl;
#pragma unroll
        for (int j = 0; j < 8; j++) {
            __nv_bfloat16 hi = __float2bfloat16(xs[j]);
            vh.h[j] = hi;
            vl.h[j] = __float2bfloat16(xs[j] - __bfloat162float(hi));
        }
        size_t o = ((size_t)kb * 1024 + m) * 1024 + 512 + k;
        *(uint4*)&g_ahi[o] = vh.u;
        *(uint4*)&g_alo[o] = vl.u;
    }
}

// =====================================================================
// K2M: LSTM gate GEMM (mma.sync bf16, hi/lo 3 passes), proven config.
// =====================================================================
#define K2_STG   32768
#define K2_SMEM  (3 * K2_STG)
#define OFF_AH   0
#define OFF_AL   8192
#define OFF_BH   16384
#define OFF_BL   24576

__global__ void __launch_bounds__(256, 2) k2m_gemm()
{
    extern __shared__ char smem[];
    const int tid = threadIdx.x;
    const int wid = tid >> 5;
    const int lid = tid & 31;
    const uint32_t sbase = smem_u32(smem);
    const int nb = blockIdx.x * 128;
    const int mb = blockIdx.y * 128;
    const int kb = blockIdx.z;

    const __nv_bfloat16* Ah = g_ahi + ((size_t)kb * 1024 + mb) * 1024;
    const __nv_bfloat16* Al = g_alo + ((size_t)kb * 1024 + mb) * 1024;
    const __nv_bfloat16* Bh = g_bhi + ((size_t)kb * 2048 + nb) * 1024;
    const __nv_bfloat16* Bl = g_blo + ((size_t)kb * 2048 + nb) * 1024;

    const int mw = (wid >> 2) * 64;
    const int nw = (wid & 3) * 32;
    const int g  = lid >> 3;
    const int r  = lid & 7;

    uint32_t offA[4][2], offB[2][2];
#pragma unroll
    for (int i = 0; i < 4; i++)
#pragma unroll
        for (int ks = 0; ks < 2; ks++) {
            int m = mw + i * 16 + (g & 1) * 8 + r;
            int k = ks * 16 + (g >> 1) * 8;
            offA[i][ks] = swz64((uint32_t)(m * 64 + k * 2));
        }
#pragma unroll
    for (int j = 0; j < 2; j++)
#pragma unroll
        for (int ks = 0; ks < 2; ks++) {
            int n = nw + j * 16 + (g & 1) * 8 + r;
            int k = ks * 16 + (g >> 1) * 8;
            offB[j][ks] = swz64((uint32_t)(n * 64 + k * 2));
        }

    float acc[4][4][4];
#pragma unroll
    for (int i = 0; i < 4; i++)
#pragma unroll
        for (int j = 0; j < 4; j++)
#pragma unroll
            for (int c = 0; c < 4; c++) acc[i][j][c] = 0.f;

    const int c_row0 = tid >> 2;
    const int c_sl   = tid & 3;
    const uint32_t c_d0 = swz64((uint32_t)(c_row0 * 64 + c_sl * 16));
    const uint32_t c_d1 = swz64((uint32_t)((c_row0 + 64) * 64 + c_sl * 16));
    const size_t  c_g0 = (size_t)c_row0 * 1024 + c_sl * 8;
    const size_t  c_g1 = (size_t)(c_row0 + 64) * 1024 + c_sl * 8;

#pragma unroll
    for (int pc = 0; pc < 2; pc++) {
        uint32_t sb = sbase + pc * K2_STG;
        int kc = pc * 32;
        cpa16(sb + OFF_AH + c_d0, Ah + c_g0 + kc);
        cpa16(sb + OFF_AL + c_d0, Al + c_g0 + kc);
        cpa16(sb + OFF_BH + c_d0, Bh + c_g0 + kc);
        cpa16(sb + OFF_BL + c_d0, Bl + c_g0 + kc);
        cpa16(sb + OFF_AH + c_d1, Ah + c_g1 + kc);
        cpa16(sb + OFF_AL + c_d1, Al + c_g1 + kc);
        cpa16(sb + OFF_BH + c_d1, Bh + c_g1 + kc);
        cpa16(sb + OFF_BL + c_d1, Bl + c_g1 + kc);
        cp_commit();
    }

    int stage = 0;
    int pstage = 2;
    for (int ch = 0; ch < 32; ch++) {
        if (ch + 1 < 32) cp_wait1(); else cp_wait0();
        __syncthreads();

        if (ch + 2 < 32) {
            uint32_t sb = sbase + pstage * K2_STG;
            int kc = (ch + 2) * 32;
            cpa16(sb + OFF_AH + c_d0, Ah + c_g0 + kc);
            cpa16(sb + OFF_AL + c_d0, Al + c_g0 + kc);
            cpa16(sb + OFF_BH + c_d0, Bh + c_g0 + kc);
            cpa16(sb + OFF_BL + c_d0, Bl + c_g0 + kc);
            cpa16(sb + OFF_AH + c_d1, Ah + c_g1 + kc);
            cpa16(sb + OFF_AL + c_d1, Al + c_g1 + kc);
            cpa16(sb + OFF_BH + c_d1, Bh + c_g1 + kc);
            cpa16(sb + OFF_BL + c_d1, Bl + c_g1 + kc);
            cp_commit();
        }

        uint32_t sb = sbase + stage * K2_STG;
#pragma unroll
        for (int ks = 0; ks < 2; ks++) {
            uint32_t bh[2][4], bl[2][4];
#pragma unroll
            for (int j = 0; j < 2; j++) {
                ldsm_x4(sb + OFF_BH + offB[j][ks], bh[j]);
                ldsm_x4(sb + OFF_BL + offB[j][ks], bl[j]);
            }
#pragma unroll
            for (int i = 0; i < 4; i++) {
                uint32_t ah[4], al[4];
                ldsm_x4(sb + OFF_AH + offA[i][ks], ah);
                ldsm_x4(sb + OFF_AL + offA[i][ks], al);
#pragma unroll
                for (int jn = 0; jn < 4; jn++) {
                    const int jj = jn >> 1;
                    const int ss = jn & 1;
                    mma_bf16(acc[i][jn], ah, bh[jj][ss], bh[jj][ss + 2]);
                    mma_bf16(acc[i][jn], ah, bl[jj][ss], bl[jj][ss + 2]);
                    mma_bf16(acc[i][jn], al, bh[jj][ss], bh[jj][ss + 2]);
                }
            }
        }
        stage  = (stage == 2) ? 0 : stage + 1;
        pstage = (pstage == 2) ? 0 : pstage + 1;
    }

    const int rowc = lid >> 2;
    const int colc = (lid & 3) * 2;
#pragma unroll
    for (int i = 0; i < 4; i++) {
        int m0 = mb + mw + i * 16 + rowc;
#pragma unroll
        for (int jn = 0; jn < 4; jn++) {
            int n0 = nb + nw + jn * 8 + colc;
            *(float2*)&g_gates[((size_t)m0 * NBO + kb) * GATES + n0] =
                make_float2(acc[i][jn][0], acc[i][jn][1]);
            *(float2*)&g_gates[((size_t)(m0 + 8) * NBO + kb) * GATES + n0] =
                make_float2(acc[i][jn][2], acc[i][jn][3]);
        }
    }
}

// =====================================================================
// K3: LSTM elementwise, float4-vectorized (4 d per thread).
// =====================================================================
__global__ void __launch_bounds__(256) k3_lstm_ew(
    const float* __restrict__ cx, const float* __restrict__ b_ih,
    const float* __restrict__ b_hh, float* __restrict__ cx_out)
{
    size_t i4 = (size_t)blockIdx.x * blockDim.x + threadIdx.x;
    size_t bk = i4 >> 7;
    int kb = (int)(bk & 7);
    int d  = (int)(i4 & 127) * 4;
    const float* g  = &g_gates[bk * GATES];
    const float* bi = &b_ih[(size_t)kb * GATES];
    const float* bh = &b_hh[(size_t)kb * GATES];

    float4 gi = *(const float4*)&g[d];
    float4 gf = *(const float4*)&g[d + 512];
    float4 gg = *(const float4*)&g[d + 1024];
    float4 go = *(const float4*)&g[d + 1536];
    float4 bi_i = *(const float4*)&bi[d],        bh_i = *(const float4*)&bh[d];
    float4 bi_f = *(const float4*)&bi[d + 512],  bh_f = *(const float4*)&bh[d + 512];
    float4 bi_g = *(const float4*)&bi[d + 1024], bh_g = *(const float4*)&bh[d + 1024];
    float4 bi_o = *(const float4*)&bi[d + 1536], bh_o = *(const float4*)&bh[d + 1536];
    float4 cb = *(const float4*)&cx[bk * BSO + d];
    float m = g_mblk[bk];

    float hn[4], co[4];
    float giv[4] = {gi.x, gi.y, gi.z, gi.w};
    float gfv[4] = {gf.x, gf.y, gf.z, gf.w};
    float ggv[4] = {gg.x, gg.y, gg.z, gg.w};
    float gov[4] = {go.x, go.y, go.z, go.w};
    float biiv[4] = {bi_i.x, bi_i.y, bi_i.z, bi_i.w};
    float bhiv[4] = {bh_i.x, bh_i.y, bh_i.z, bh_i.w};
    float bifv[4] = {bi_f.x, bi_f.y, bi_f.z, bi_f.w};
    float bhfv[4] = {bh_f.x, bh_f.y, bh_f.z, bh_f.w};
    float bigv[4] = {bi_g.x, bi_g.y, bi_g.z, bi_g.w};
    float bhgv[4] = {bh_g.x, bh_g.y, bh_g.z, bh_g.w};
    float biov[4] = {bi_o.x, bi_o.y, bi_o.z, bi_o.w};
    float bhov[4] = {bh_o.x, bh_o.y, bh_o.z, bh_o.w};
    float cbv[4] = {cb.x, cb.y, cb.z, cb.w};
#pragma unroll
    for (int j = 0; j < 4; j++) {
        float ig = sigf(giv[j] + biiv[j] + bhiv[j]);
        float fg = sigf(gfv[j] + bifv[j] + bhfv[j]);
        float gt = tanhf(ggv[j] + bigv[j] + bhgv[j]);
        float og = sigf(gov[j] + biov[j] + bhov[j]);
        float cn = fg * cbv[j] + ig * gt;
        hn[j] = og * tanhf(cn);
        co[j] = m * cn + (1.0f - m) * cbv[j];
    }
    *(float4*)&g_hnew[bk * BSO + d]  = make_float4(hn[0], hn[1], hn[2], hn[3]);
    *(float4*)&cx_out[bk * BSO + d] = make_float4(co[0], co[1], co[2], co[3]);
}

// =====================================================================
// K4: q2/k2/v2 GEMMs.  Tile 128x64, 8m x 4n microtile, FFMA2.
//   grid (3, 8, 8) = 192 CTAs.
// =====================================================================
__global__ void __launch_bounds__(256) k4_qkv(
    const float* __restrict__ wq, const float* __restrict__ wk, const float* __restrict__ wv)
{
    __shared__ float hs[128][36];
    __shared__ float ws[32][64];

    const int tid = threadIdx.x;
    const int mat = blockIdx.x;
    const int m0  = blockIdx.y * 128;
    const int kb  = blockIdx.z;
    const int tx  = tid & 15;
    const int ty  = tid >> 4;
    const int n4  = tx * 4;
    const int m8  = ty * 8;

    const float* w = ((mat == 0) ? wq : (mat == 1) ? wk : wv) + (size_t)kb * BSO * DKQ;

    unsigned long long acc[8][2];
#pragma unroll
    for (int j = 0; j < 8; j++) { acc[j][0] = 0ULL; acc[j][1] = 0ULL; }

    for (int kc = 0; kc < BSO; kc += 32) {
#pragma unroll
        for (int p = 0; p < 16; p++) {
            int idx = p * 256 + tid;
            int r  = idx >> 5;
            int kk = idx & 31;
            hs[r][kk] = g_hnew[((size_t)(m0 + r) * NBO + kb) * BSO + kc + kk];
        }
#pragma unroll
        for (int p = 0; p < 8; p++) {
            int idx = p * 256 + tid;
            int kk = idx >> 6;
            int n  = idx & 63;
            ws[kk][n] = w[(size_t)(kc + kk) * DKQ + n];
        }
        __syncthreads();

#pragma unroll
        for (int kk4 = 0; kk4 < 32; kk4 += 4) {
            float4 a[8];
#pragma unroll
            for (int j = 0; j < 8; j++) a[j] = *(const float4*)&hs[m8 + j][kk4];
#pragma unroll
            for (int t = 0; t < 4; t++) {
                float4 wv4 = *(const float4*)&ws[kk4 + t][n4];
                unsigned long long b0 = pk2(wv4.x, wv4.y);
                unsigned long long b1 = pk2(wv4.z, wv4.w);
#pragma unroll
                for (int j = 0; j < 8; j++) {
                    float av = (t == 0) ? a[j].x : (t == 1) ? a[j].y
                             : (t == 2) ? a[j].z : a[j].w;
                    unsigned long long aa = pk2(av, av);
                    fma2(acc[j][0], aa, b0);
                    fma2(acc[j][1], aa, b1);
                }
            }
        }
        __syncthreads();
    }

    float* dst = (mat == 0) ? g_q2 : (mat == 1) ? g_k2 : g_v2;
#pragma unroll
    for (int j = 0; j < 8; j++) {
        float2 c0 = upk2(acc[j][0]);
        float2 c1 = upk2(acc[j][1]);
        float4 v = make_float4(c0.x, c0.y, c1.x, c1.y);
        *(float4*)&dst[((size_t)(m0 + m8 + j) * NBO + kb) * DKQ + n4] = v;
    }
}

// =====================================================================
// K5: MHA attend + fc/gate + final hx_out combine.  4 batches per CTA
//   (weights read once per CTA, L1-reused across batches).
// =====================================================================
#define K5_BPB 4
__global__ void __launch_bounds__(256) k5_mha(
    const float* __restrict__ hx,
    const float* __restrict__ fcw, const float* __restrict__ fcb,
    const float* __restrict__ gw,  const float* __restrict__ gb,
    float* __restrict__ hx_out)
{
    __shared__ float sq2[K5_BPB][NBO][DKQ];
    __shared__ float sk2[K5_BPB][NBO][DKQ];
    __shared__ float sv2[K5_BPB][NBO][DKQ];
    __shared__ float sat[K5_BPB][NBO][NBO];
    __shared__ float so2[K5_BPB][NBO][DKQ];

    const int tid = threadIdx.x;
    const size_t b0 = (size_t)blockIdx.x * K5_BPB;

    for (int i = tid; i < K5_BPB * NBO * DKQ; i += 256) {
        int bi = i / (NBO * DKQ);
        int r  = i % (NBO * DKQ);
        ((float*)sq2[bi])[r] = g_q2[(b0 + bi) * NBO * DKQ + r];
        ((float*)sk2[bi])[r] = g_k2[(b0 + bi) * NBO * DKQ + r];
        ((float*)sv2[bi])[r] = g_v2[(b0 + bi) * NBO * DKQ + r];
    }
    __syncthreads();

    // scores: 256 threads = 4 bi x 64 (kq, kj)
    {
        int bi = tid >> 6;
        int kq = (tid >> 3) & 7;
        int kj = tid & 7;
        float s = 0.f;
        for (int e = 0; e < DKQ; e++) s += sq2[bi][kq][e] * sk2[bi][kj][e];
        sat[bi][kq][kj] = s * 0.125f;
    }
    __syncthreads();
    if (tid < K5_BPB * NBO) {
        int bi = tid >> 3, k = tid & 7;
        float mx = -1e30f;
        for (int j = 0; j < NBO; j++) mx = fmaxf(mx, sat[bi][k][j]);
        float den = 0.f;
        for (int j = 0; j < NBO; j++) { float e = expf(sat[bi][k][j] - mx); sat[bi][k][j] = e; den += e; }
        float inv = 1.0f / den;
        for (int j = 0; j < NBO; j++) sat[bi][k][j] *= inv;
    }
    __syncthreads();
    for (int i = tid; i < K5_BPB * NBO * DKQ; i += 256) {
        int bi = i / (NBO * DKQ);
        int r  = i % (NBO * DKQ);
        int k = r >> 6, e = r & 63;
        float a = 0.f;
        for (int j = 0; j < NBO; j++) a += sat[bi][k][j] * sv2[bi][j][e];
        so2[bi][k][e] = a;
    }
    __syncthreads();

    const int d0 = tid * 2;
    const float fb0 = fcb[d0], fb1 = fcb[d0 + 1];
    const float gb0 = gb[d0],  gb1 = gb[d0 + 1];

    for (int bi = 0; bi < K5_BPB; bi++) {
        float2 ao[NBO], ag[NBO];
#pragma unroll
        for (int k = 0; k < NBO; k++) { ao[k] = make_float2(0.f, 0.f); ag[k] = make_float2(0.f, 0.f); }

        for (int e = 0; e < DKQ; e++) {
            float2 fw  = *(const float2*)&fcw[(size_t)e * BSO + d0];
            float2 gwv = *(const float2*)&gw[(size_t)e * BSO + d0];
#pragma unroll
            for (int k = 0; k < NBO; k++) {
                float o = so2[bi][k][e];
                ao[k].x += o * fw.x;  ao[k].y += o * fw.y;
                ag[k].x += o * gwv.x; ag[k].y += o * gwv.y;
            }
        }

        const size_t b = b0 + bi;
#pragma unroll
        for (int k = 0; k < NBO; k++) {
            float m = g_mblk[b * NBO + k];
            float hn0 = g_hnew[(b * NBO + k) * BSO + d0];
            float hn1 = g_hnew[(b * NBO + k) * BSO + d0 + 1];
            float v0 = hn0 + sigf(ag[k].x + gb0) * tanhf(ao[k].x + fb0);
            float v1 = hn1 + sigf(ag[k].y + gb1) * tanhf(ao[k].y + fb1);
            size_t idx = b * NHID + (size_t)k * BSO + d0;
            hx_out[idx]     = m * v0 + (1.0f - m) * hx[idx];
            hx_out[idx + 1] = m * v1 + (1.0f - m) * hx[idx + 1];
        }
    }
}

// =====================================================================
extern "C" void kernel_launch(void* const* d_in, const int* in_sizes, int n_in,
                              void* d_out, int out_size) {
    const float* inp    = (const float*)d_in[0];
    const float* hx     = (const float*)d_in[1];
    const float* cx     = (const float*)d_in[2];
    const float* ia_wq  = (const float*)d_in[3];
    const float* ia_wk  = (const float*)d_in[4];
    const float* ia_wv  = (const float*)d_in[5];
    const float* ia_fcw = (const float*)d_in[6];
    const float* ia_fcb = (const float*)d_in[7];
    const float* mha_wq = (const float*)d_in[8];
    const float* mha_wk = (const float*)d_in[9];
    const float* mha_wv = (const float*)d_in[10];
    const float* mha_fcw= (const float*)d_in[11];
    const float* mha_fcb= (const float*)d_in[12];
    const float* mha_gw = (const float*)d_in[13];
    const float* mha_gb = (const float*)d_in[14];
    const float* w_ih   = (const float*)d_in[15];
    const float* w_hh   = (const float*)d_in[16];
    const float* b_ih   = (const float*)d_in[17];
    const float* b_hh   = (const float*)d_in[18];

    float* out   = (float*)d_out;
    const size_t N = (size_t)BSZ * NHID;
    float* out_hx   = out;
    float* out_cx   = out + N;
    float* out_mask = out + 2 * N;

    cudaFuncSetAttribute(k2m_gemm, cudaFuncAttributeMaxDynamicSharedMemorySize, K2_SMEM);

    k_pre<<<PRE_BLOCKS, 256>>>(inp, hx, ia_wq, ia_wk, ia_wv, ia_fcw, ia_fcb,
                               w_ih, w_hh, out_mask);
    k2m_gemm<<<dim3(GATES / 128, BSZ / 128, NBO), 256, K2_SMEM>>>();
    k3_lstm_ew<<<(unsigned)(((size_t)BSZ * NBO * BSO / 4 + 255) / 256), 256>>>(cx, b_ih, b_hh, out_cx);
    k4_qkv<<<dim3(3, BSZ / 128, NBO), 256>>>(mha_wq, mha_wk, mha_wv);
    k5_mha<<<BSZ / K5_BPB, 256>>>(hx, mha_fcw, mha_fcb, mha_gw, mha_gb, out_hx);
}

// round 12
// speedup vs baseline: 1.0446x; 1.0446x over previous
#include <cuda_runtime.h>
#include <cuda_bf16.h>
#include <math.h>
#include <stdint.h>

#define BSZ   1024
#define NBIN  4
#define BSIN  128
#define NKEY  5
#define NBO   8
#define BSO   512
#define NHID  4096
#define DKQ   64
#define GATES 2048

// ------------- scratch (allocation-free: __device__ globals) -------------
__device__ float g_gates  [(size_t)BSZ * NBO * GATES];
__device__ float g_hnew   [(size_t)BSZ * NBO * BSO];
__device__ float g_q2     [(size_t)BSZ * NBO * DKQ];
__device__ float g_k2     [(size_t)BSZ * NBO * DKQ];
__device__ float g_v2     [(size_t)BSZ * NBO * DKQ];
__device__ float g_mblk   [(size_t)BSZ * NBO];
// bf16 hi/lo split operands for the tensor-core LSTM GEMM
__device__ __nv_bfloat16 g_ahi[(size_t)NBO * 1024 * 1024];
__device__ __nv_bfloat16 g_alo[(size_t)NBO * 1024 * 1024];
__device__ __nv_bfloat16 g_bhi[(size_t)NBO * 2048 * 1024];
__device__ __nv_bfloat16 g_blo[(size_t)NBO * 2048 * 1024];

__device__ __forceinline__ float sigf(float x) { return 1.0f / (1.0f + expf(-x)); }

// ------------- f32x2 packed FMA helpers -------------
__device__ __forceinline__ unsigned long long pk2(float x, float y) {
    unsigned long long r;
    asm("mov.b64 %0, {%1, %2};" : "=l"(r) : "f"(x), "f"(y));
    return r;
}
__device__ __forceinline__ void fma2(unsigned long long& d, unsigned long long a, unsigned long long b) {
    asm("fma.rn.f32x2 %0, %1, %2, %0;" : "+l"(d) : "l"(a), "l"(b));
}
__device__ __forceinline__ float2 upk2(unsigned long long v) {
    float2 f;
    asm("mov.b64 {%0, %1}, %2;" : "=f"(f.x), "=f"(f.y) : "l"(v));
    return f;
}

// ------------- mma.sync / ldmatrix / cp.async helpers -------------
__device__ __forceinline__ uint32_t smem_u32(const void* p) {
    uint32_t a;
    asm("{ .reg .u64 t; cvta.to.shared.u64 t, %1; cvt.u32.u64 %0, t; }" : "=r"(a) : "l"(p));
    return a;
}
__device__ __forceinline__ uint32_t swz64(uint32_t b) { return b ^ ((b >> 3) & 0x30); }

__device__ __forceinline__ void ldsm_x4(uint32_t addr, uint32_t* r) {
    asm volatile("ldmatrix.sync.aligned.m8n8.x4.shared.b16 {%0,%1,%2,%3}, [%4];"
                 : "=r"(r[0]), "=r"(r[1]), "=r"(r[2]), "=r"(r[3]) : "r"(addr));
}
__device__ __forceinline__ void mma_bf16(float* c, const uint32_t* a, uint32_t b0, uint32_t b1) {
    asm volatile("mma.sync.aligned.m16n8k16.row.col.f32.bf16.bf16.f32 "
                 "{%0,%1,%2,%3}, {%4,%5,%6,%7}, {%8,%9}, {%0,%1,%2,%3};"
                 : "+f"(c[0]), "+f"(c[1]), "+f"(c[2]), "+f"(c[3])
                 : "r"(a[0]), "r"(a[1]), "r"(a[2]), "r"(a[3]), "r"(b0), "r"(b1));
}
__device__ __forceinline__ void cpa16(uint32_t dst, const void* src) {
    asm volatile("cp.async.cg.shared.global [%0], [%1], 16;" :: "r"(dst), "l"(src));
}
__device__ __forceinline__ void cp_commit() { asm volatile("cp.async.commit_group;"); }
__device__ __forceinline__ void cp_wait1() { asm volatile("cp.async.wait_group 1;"); }
__device__ __forceinline__ void cp_wait0() { asm volatile("cp.async.wait_group 0;"); }

// =====================================================================
// K_PRE: fused (k1 input-attention | prep_b | prep_a2).
// =====================================================================
#define K1_BPB 4
#define K1_BLOCKS   (BSZ / K1_BPB)                /* 256  */
#define PB_BLOCKS   (32 * 16 * 8)                 /* 4096 */
#define PA_BLOCKS   2048
#define PRE_BLOCKS  (K1_BLOCKS + PB_BLOCKS + PA_BLOCKS)

struct K1Smem {
    float sx[K1_BPB][NKEY * BSIN];
    float sk[K1_BPB][NKEY][DKQ];
    float sv[K1_BPB][NKEY][DKQ];
    float sq[K1_BPB][NBO][DKQ];
    float so[K1_BPB][NBO][DKQ];
    float sattn[K1_BPB][NBO][NKEY];
    float smb[K1_BPB][NBO];
};
union PreSmem {
    K1Smem k1;
    float ts[64][65];
};

__global__ void __launch_bounds__(256) k_pre(
    const float* __restrict__ inp, const float* __restrict__ hx,
    const float* __restrict__ wq, const float* __restrict__ wk, const float* __restrict__ wv,
    const float* __restrict__ fcw, const float* __restrict__ fcb,
    const float* __restrict__ w_ih, const float* __restrict__ w_hh,
    float* __restrict__ mask_out)
{
    __shared__ PreSmem su;
    const int tid = threadIdx.x;
    const int bid = blockIdx.x;

    if (bid < K1_BLOCKS) {
        auto& sx = su.k1.sx;  auto& sk = su.k1.sk;  auto& sv = su.k1.sv;
        auto& sq = su.k1.sq;  auto& so = su.k1.so;
        auto& sattn = su.k1.sattn;  auto& smb = su.k1.smb;
        const int b0 = bid * K1_BPB;

        for (int i = tid; i < K1_BPB * NKEY * BSIN; i += 256) {
            int bi = i / (NKEY * BSIN);
            int j  = i % (NKEY * BSIN);
            sx[bi][j] = (j < NBIN * BSIN) ? inp[(size_t)(b0 + bi) * (NBIN * BSIN) + j] : 0.0f;
        }
        __syncthreads();

        if (tid < 128) {
            const int n  = tid >> 4;
            const int e4 = (tid & 15) * 4;
            const float* wp = wq + (size_t)(n * BSO) * DKQ + e4;
            float4 aq[K1_BPB];
#pragma unroll
            for (int bi = 0; bi < K1_BPB; bi++) aq[bi] = make_float4(0.f, 0.f, 0.f, 0.f);
#pragma unroll 4
            for (int d = 0; d < BSO; d++) {
                float4 w4 = *(const float4*)(wp + (size_t)d * DKQ);
#pragma unroll
                for (int bi = 0; bi < K1_BPB; bi++) {
                    float hv = __ldg(&hx[(size_t)(b0 + bi) * NHID + n * BSO + d]);
                    aq[bi].x += hv * w4.x; aq[bi].y += hv * w4.y;
                    aq[bi].z += hv * w4.z; aq[bi].w += hv * w4.w;
                }
            }
#pragma unroll
            for (int bi = 0; bi < K1_BPB; bi++) *(float4*)&sq[bi][n][e4] = aq[bi];
        } else if (tid < 128 + NKEY * 16) {
            const int g  = tid - 128;
            const int n  = g / 16;
            const int e4 = (g % 16) * 4;
            const float* wkp = wk + (size_t)(n * BSIN) * DKQ + e4;
            const float* wvp = wv + (size_t)(n * BSIN) * DKQ + e4;
            float4 ak[K1_BPB], av[K1_BPB];
#pragma unroll
            for (int bi = 0; bi < K1_BPB; bi++) {
                ak[bi] = make_float4(0.f, 0.f, 0.f, 0.f);
                av[bi] = make_float4(0.f, 0.f, 0.f, 0.f);
            }
#pragma unroll 4
            for (int d = 0; d < BSIN; d++) {
                float4 a4 = *(const float4*)(wkp + (size_t)d * DKQ);
                float4 b4 = *(const float4*)(wvp + (size_t)d * DKQ);
#pragma unroll
                for (int bi = 0; bi < K1_BPB; bi++) {
                    float xv = sx[bi][n * BSIN + d];
                    ak[bi].x += xv * a4.x; ak[bi].y += xv * a4.y;
                    ak[bi].z += xv * a4.z; ak[bi].w += xv * a4.w;
                    av[bi].x += xv * b4.x; av[bi].y += xv * b4.y;
                    av[bi].z += xv * b4.z; av[bi].w += xv * b4.w;
                }
            }
#pragma unroll
            for (int bi = 0; bi < K1_BPB; bi++) {
                *(float4*)&sk[bi][n][e4] = ak[bi];
                *(float4*)&sv[bi][n][e4] = av[bi];
            }
        }
        __syncthreads();

        if (tid < K1_BPB * NBO) {
            int bi = tid / NBO, n = tid % NBO;
            float s[NKEY];
            float mx = -1e30f;
            for (int j = 0; j < NKEY; j++) {
                float a = 0.f;
                for (int e = 0; e < DKQ; e++) a += sq[bi][n][e] * sk[bi][j][e];
                a *= 0.125f;
                s[j] = a;
                mx = fmaxf(mx, a);
            }
            float den = 0.f;
            for (int j = 0; j < NKEY; j++) { s[j] = expf(s[j] - mx); den += s[j]; }
            float inv = 1.0f / den;
            for (int j = 0; j < NKEY; j++) sattn[bi][n][j] = s[j] * inv;
        }
        __syncthreads();

        if (tid < K1_BPB) {
            int bi = tid;
            float sc[NBO], t[NBO];
            for (int n = 0; n < NBO; n++) { sc[n] = sattn[bi][n][0]; t[n] = sc[n]; }
            for (int a = 0; a < 4; a++) {
                int mi = a;
                for (int b = a + 1; b < NBO; b++) if (t[b] > t[mi]) mi = b;
                float tmp = t[a]; t[a] = t[mi]; t[mi] = tmp;
            }
            float thr = t[3] - 0.01f;
            for (int n = 0; n < NBO; n++) {
                float m = (sc[n] > thr) ? 1.0f : 0.0f;
                smb[bi][n] = m;
                g_mblk[(size_t)(b0 + bi) * NBO + n] = m;
            }
        }
        __syncthreads();

        for (int i = tid; i < K1_BPB * NBO * DKQ; i += 256) {
            int bi = i / (NBO * DKQ);
            int r  = i % (NBO * DKQ);
            int n  = r / DKQ;
            int e  = r % DKQ;
            float a = 0.f;
            for (int j = 0; j < NKEY; j++) a += sattn[bi][n][j] * sv[bi][j][e];
            so[bi][n][e] = a;
        }
        __syncthreads();

        for (int round = 0; round < 4; round++) {
            int g  = round * 256 + tid;
            int n  = g >> 7;
            int c4 = (g & 127) * 4;
            float4 bias = *(const float4*)&fcb[c4];
            float4 a[K1_BPB];
#pragma unroll
            for (int bi = 0; bi < K1_BPB; bi++) a[bi] = bias;
#pragma unroll 4
            for (int e = 0; e < DKQ; e++) {
                float4 w4 = *(const float4*)&fcw[(size_t)e * BSO + c4];
#pragma unroll
                for (int bi = 0; bi < K1_BPB; bi++) {
                    float s = so[bi][n][e];
                    a[bi].x += s * w4.x; a[bi].y += s * w4.y;
                    a[bi].z += s * w4.z; a[bi].w += s * w4.w;
                }
            }
#pragma unroll
            for (int bi = 0; bi < K1_BPB; bi++) {
                float xs[4] = {a[bi].x, a[bi].y, a[bi].z, a[bi].w};
                union { __nv_bfloat16 h[4]; uint2 u; } vh, vl;
#pragma unroll
                for (int j = 0; j < 4; j++) {
                    __nv_bfloat16 hi = __float2bfloat16(xs[j]);
                    vh.h[j] = hi;
                    vl.h[j] = __float2bfloat16(xs[j] - __bfloat162float(hi));
                }
                size_t ao = ((size_t)n * 1024 + (b0 + bi)) * 1024 + c4;
                *(uint2*)&g_ahi[ao] = vh.u;
                *(uint2*)&g_alo[ao] = vl.u;
                float m = smb[bi][n];
                *(float4*)&mask_out[(size_t)(b0 + bi) * NHID + n * BSO + c4] = make_float4(m, m, m, m);
            }
        }
    } else if (bid < K1_BLOCKS + PB_BLOCKS) {
        auto& ts = su.ts;
        const int pb = bid - K1_BLOCKS;
        const int n0 = (pb & 31) * 64;
        const int k0 = ((pb >> 5) & 15) * 64;
        const int kb = pb >> 9;

        const float* srcm = (k0 < 512) ? (w_ih + (size_t)kb * 512 * GATES)
                                       : (w_hh + (size_t)kb * 512 * GATES);
        const int krow0 = (k0 < 512) ? k0 : (k0 - 512);

#pragma unroll
        for (int p = 0; p < 16; p++) {
            int idx = p * 256 + tid;
            int r = idx >> 6;
            int c = idx & 63;
            ts[r][c] = srcm[(size_t)(krow0 + r) * GATES + n0 + c];
        }
        __syncthreads();

#pragma unroll
        for (int g = 0; g < 2; g++) {
            int n   = (tid >> 3) + g * 32;
            int kk0 = (tid & 7) * 8;
            union { __nv_bfloat16 h[8]; uint4 u; } vh, vl;
#pragma unroll
            for (int j = 0; j < 8; j++) {
                float x = ts[kk0 + j][n];
                __nv_bfloat16 hi = __float2bfloat16(x);
                vh.h[j] = hi;
                vl.h[j] = __float2bfloat16(x - __bfloat162float(hi));
            }
            size_t o = ((size_t)kb * GATES + n0 + n) * 1024 + k0 + kk0;
            *(uint4*)&g_bhi[o] = vh.u;
            *(uint4*)&g_blo[o] = vl.u;
        }
    } else {
        size_t idx = (size_t)(bid - K1_BLOCKS - PB_BLOCKS) * 256 + tid;
        int k8 = (int)(idx & 63);
        int m  = (int)((idx >> 6) & 1023);
        int kb = (int)(idx >> 16);
        int k  = k8 * 8;

        const float* src = &hx[(size_t)m * NHID + kb * BSO + k];
        float4 a = *(const float4*)src;
        float4 b = *(const float4*)(src + 4);
        float xs[8] = {a.x, a.y, a.z, a.w, b.x, b.y, b.z, b.w};
        union { __nv_bfloat16 h[8]; uint4 u; } vh, vl;
#pragma unroll
        for (int j = 0; j < 8; j++) {
            __nv_bfloat16 hi = __float2bfloat16(xs[j]);
            vh.h[j] = hi;
            vl.h[j] = __float2bfloat16(xs[j] - __bfloat162float(hi));
        }
        size_t o = ((size_t)kb * 1024 + m) * 1024 + 512 + k;
        *(uint4*)&g_ahi[o] = vh.u;
        *(uint4*)&g_alo[o] = vl.u;
    }
}

// =====================================================================
// K2M: LSTM gate GEMM (mma.sync bf16, hi/lo 3 passes), proven config.
// =====================================================================
#define K2_STG   32768
#define K2_SMEM  (3 * K2_STG)
#define OFF_AH   0
#define OFF_AL   8192
#define OFF_BH   16384
#define OFF_BL   24576

__global__ void __launch_bounds__(256, 2) k2m_gemm()
{
    extern __shared__ char smem[];
    const int tid = threadIdx.x;
    const int wid = tid >> 5;
    const int lid = tid & 31;
    const uint32_t sbase = smem_u32(smem);
    const int nb = blockIdx.x * 128;
    const int mb = blockIdx.y * 128;
    const int kb = blockIdx.z;

    const __nv_bfloat16* Ah = g_ahi + ((size_t)kb * 1024 + mb) * 1024;
    const __nv_bfloat16* Al = g_alo + ((size_t)kb * 1024 + mb) * 1024;
    const __nv_bfloat16* Bh = g_bhi + ((size_t)kb * 2048 + nb) * 1024;
    const __nv_bfloat16* Bl = g_blo + ((size_t)kb * 2048 + nb) * 1024;

    const int mw = (wid >> 2) * 64;
    const int nw = (wid & 3) * 32;
    const int g  = lid >> 3;
    const int r  = lid & 7;

    uint32_t offA[4][2], offB[2][2];
#pragma unroll
    for (int i = 0; i < 4; i++)
#pragma unroll
        for (int ks = 0; ks < 2; ks++) {
            int m = mw + i * 16 + (g & 1) * 8 + r;
            int k = ks * 16 + (g >> 1) * 8;
            offA[i][ks] = swz64((uint32_t)(m * 64 + k * 2));
        }
#pragma unroll
    for (int j = 0; j < 2; j++)
#pragma unroll
        for (int ks = 0; ks < 2; ks++) {
            int n = nw + j * 16 + (g & 1) * 8 + r;
            int k = ks * 16 + (g >> 1) * 8;
            offB[j][ks] = swz64((uint32_t)(n * 64 + k * 2));
        }

    float acc[4][4][4];
#pragma unroll
    for (int i = 0; i < 4; i++)
#pragma unroll
        for (int j = 0; j < 4; j++)
#pragma unroll
            for (int c = 0; c < 4; c++) acc[i][j][c] = 0.f;

    const int c_row0 = tid >> 2;
    const int c_sl   = tid & 3;
    const uint32_t c_d0 = swz64((uint32_t)(c_row0 * 64 + c_sl * 16));
    const uint32_t c_d1 = swz64((uint32_t)((c_row0 + 64) * 64 + c_sl * 16));
    const size_t  c_g0 = (size_t)c_row0 * 1024 + c_sl * 8;
    const size_t  c_g1 = (size_t)(c_row0 + 64) * 1024 + c_sl * 8;

#pragma unroll
    for (int pc = 0; pc < 2; pc++) {
        uint32_t sb = sbase + pc * K2_STG;
        int kc = pc * 32;
        cpa16(sb + OFF_AH + c_d0, Ah + c_g0 + kc);
        cpa16(sb + OFF_AL + c_d0, Al + c_g0 + kc);
        cpa16(sb + OFF_BH + c_d0, Bh + c_g0 + kc);
        cpa16(sb + OFF_BL + c_d0, Bl + c_g0 + kc);
        cpa16(sb + OFF_AH + c_d1, Ah + c_g1 + kc);
        cpa16(sb + OFF_AL + c_d1, Al + c_g1 + kc);
        cpa16(sb + OFF_BH + c_d1, Bh + c_g1 + kc);
        cpa16(sb + OFF_BL + c_d1, Bl + c_g1 + kc);
        cp_commit();
    }

    int stage = 0;
    int pstage = 2;
    for (int ch = 0; ch < 32; ch++) {
        if (ch + 1 < 32) cp_wait1(); else cp_wait0();
        __syncthreads();

        if (ch + 2 < 32) {
            uint32_t sb = sbase + pstage * K2_STG;
            int kc = (ch + 2) * 32;
            cpa16(sb + OFF_AH + c_d0, Ah + c_g0 + kc);
            cpa16(sb + OFF_AL + c_d0, Al + c_g0 + kc);
            cpa16(sb + OFF_BH + c_d0, Bh + c_g0 + kc);
            cpa16(sb + OFF_BL + c_d0, Bl + c_g0 + kc);
            cpa16(sb + OFF_AH + c_d1, Ah + c_g1 + kc);
            cpa16(sb + OFF_AL + c_d1, Al + c_g1 + kc);
            cpa16(sb + OFF_BH + c_d1, Bh + c_g1 + kc);
            cpa16(sb + OFF_BL + c_d1, Bl + c_g1 + kc);
            cp_commit();
        }

        uint32_t sb = sbase + stage * K2_STG;
#pragma unroll
        for (int ks = 0; ks < 2; ks++) {
            uint32_t bh[2][4], bl[2][4];
#pragma unroll
            for (int j = 0; j < 2; j++) {
                ldsm_x4(sb + OFF_BH + offB[j][ks], bh[j]);
                ldsm_x4(sb + OFF_BL + offB[j][ks], bl[j]);
            }
#pragma unroll
            for (int i = 0; i < 4; i++) {
                uint32_t ah[4], al[4];
                ldsm_x4(sb + OFF_AH + offA[i][ks], ah);
                ldsm_x4(sb + OFF_AL + offA[i][ks], al);
#pragma unroll
                for (int jn = 0; jn < 4; jn++) {
                    const int jj = jn >> 1;
                    const int ss = jn & 1;
                    mma_bf16(acc[i][jn], ah, bh[jj][ss], bh[jj][ss + 2]);
                    mma_bf16(acc[i][jn], ah, bl[jj][ss], bl[jj][ss + 2]);
                    mma_bf16(acc[i][jn], al, bh[jj][ss], bh[jj][ss + 2]);
                }
            }
        }
        stage  = (stage == 2) ? 0 : stage + 1;
        pstage = (pstage == 2) ? 0 : pstage + 1;
    }

    const int rowc = lid >> 2;
    const int colc = (lid & 3) * 2;
#pragma unroll
    for (int i = 0; i < 4; i++) {
        int m0 = mb + mw + i * 16 + rowc;
#pragma unroll
        for (int jn = 0; jn < 4; jn++) {
            int n0 = nb + nw + jn * 8 + colc;
            *(float2*)&g_gates[((size_t)m0 * NBO + kb) * GATES + n0] =
                make_float2(acc[i][jn][0], acc[i][jn][1]);
            *(float2*)&g_gates[((size_t)(m0 + 8) * NBO + kb) * GATES + n0] =
                make_float2(acc[i][jn][2], acc[i][jn][3]);
        }
    }
}

// =====================================================================
// K3: LSTM elementwise, float4-vectorized (4 d per thread).
// =====================================================================
__global__ void __launch_bounds__(256) k3_lstm_ew(
    const float* __restrict__ cx, const float* __restrict__ b_ih,
    const float* __restrict__ b_hh, float* __restrict__ cx_out)
{
    size_t i4 = (size_t)blockIdx.x * blockDim.x + threadIdx.x;
    size_t bk = i4 >> 7;
    int kb = (int)(bk & 7);
    int d  = (int)(i4 & 127) * 4;
    const float* g  = &g_gates[bk * GATES];
    const float* bi = &b_ih[(size_t)kb * GATES];
    const float* bh = &b_hh[(size_t)kb * GATES];

    float4 gi = *(const float4*)&g[d];
    float4 gf = *(const float4*)&g[d + 512];
    float4 gg = *(const float4*)&g[d + 1024];
    float4 go = *(const float4*)&g[d + 1536];
    float4 bi_i = *(const float4*)&bi[d],        bh_i = *(const float4*)&bh[d];
    float4 bi_f = *(const float4*)&bi[d + 512],  bh_f = *(const float4*)&bh[d + 512];
    float4 bi_g = *(const float4*)&bi[d + 1024], bh_g = *(const float4*)&bh[d + 1024];
    float4 bi_o = *(const float4*)&bi[d + 1536], bh_o = *(const float4*)&bh[d + 1536];
    float4 cb = *(const float4*)&cx[bk * BSO + d];
    float m = g_mblk[bk];

    float hn[4], co[4];
    float giv[4] = {gi.x, gi.y, gi.z, gi.w};
    float gfv[4] = {gf.x, gf.y, gf.z, gf.w};
    float ggv[4] = {gg.x, gg.y, gg.z, gg.w};
    float gov[4] = {go.x, go.y, go.z, go.w};
    float biiv[4] = {bi_i.x, bi_i.y, bi_i.z, bi_i.w};
    float bhiv[4] = {bh_i.x, bh_i.y, bh_i.z, bh_i.w};
    float bifv[4] = {bi_f.x, bi_f.y, bi_f.z, bi_f.w};
    float bhfv[4] = {bh_f.x, bh_f.y, bh_f.z, bh_f.w};
    float bigv[4] = {bi_g.x, bi_g.y, bi_g.z, bi_g.w};
    float bhgv[4] = {bh_g.x, bh_g.y, bh_g.z, bh_g.w};
    float biov[4] = {bi_o.x, bi_o.y, bi_o.z, bi_o.w};
    float bhov[4] = {bh_o.x, bh_o.y, bh_o.z, bh_o.w};
    float cbv[4] = {cb.x, cb.y, cb.z, cb.w};
#pragma unroll
    for (int j = 0; j < 4; j++) {
        float ig = sigf(giv[j] + biiv[j] + bhiv[j]);
        float fg = sigf(gfv[j] + bifv[j] + bhfv[j]);
        float gt = tanhf(ggv[j] + bigv[j] + bhgv[j]);
        float og = sigf(gov[j] + biov[j] + bhov[j]);
        float cn = fg * cbv[j] + ig * gt;
        hn[j] = og * tanhf(cn);
        co[j] = m * cn + (1.0f - m) * cbv[j];
    }
    *(float4*)&g_hnew[bk * BSO + d]  = make_float4(hn[0], hn[1], hn[2], hn[3]);
    *(float4*)&cx_out[bk * BSO + d] = make_float4(co[0], co[1], co[2], co[3]);
}

// =====================================================================
// K4: q2/k2/v2 GEMMs.  Tile 64x64, K=512, FFMA2, LDS.128, 3 CTAs/SM.
// =====================================================================
__global__ void __launch_bounds__(256, 3) k4_qkv(
    const float* __restrict__ wq, const float* __restrict__ wk, const float* __restrict__ wv)
{
    __shared__ float hs[64][36];     // pad 36 -> 144B rows, 16B aligned
    __shared__ float ws[32][64];

    const int tid = threadIdx.x;
    const int mat = blockIdx.x;
    const int m0  = blockIdx.y * 64;
    const int kb  = blockIdx.z;
    const int tx  = tid & 15;
    const int ty  = tid >> 4;
    const int n4  = tx * 4;
    const int m4  = ty * 4;

    const float* w = ((mat == 0) ? wq : (mat == 1) ? wk : wv) + (size_t)kb * BSO * DKQ;

    unsigned long long acc[4][2];
#pragma unroll
    for (int j = 0; j < 4; j++) { acc[j][0] = 0ULL; acc[j][1] = 0ULL; }

    for (int kc = 0; kc < BSO; kc += 32) {
#pragma unroll
        for (int p = 0; p < 8; p++) {
            int idx = p * 256 + tid;
            int r  = idx >> 5;
            int kk = idx & 31;
            hs[r][kk] = g_hnew[((size_t)(m0 + r) * NBO + kb) * BSO + kc + kk];
        }
#pragma unroll
        for (int p = 0; p < 8; p++) {
            int idx = p * 256 + tid;
            int kk = idx >> 6;
            int n  = idx & 63;
            ws[kk][n] = w[(size_t)(kc + kk) * DKQ + n];
        }
        __syncthreads();

#pragma unroll
        for (int kk4 = 0; kk4 < 32; kk4 += 4) {
            float4 a0 = *(const float4*)&hs[m4 + 0][kk4];
            float4 a1 = *(const float4*)&hs[m4 + 1][kk4];
            float4 a2 = *(const float4*)&hs[m4 + 2][kk4];
            float4 a3 = *(const float4*)&hs[m4 + 3][kk4];
#pragma unroll
            for (int t = 0; t < 4; t++) {
                float4 wv4 = *(const float4*)&ws[kk4 + t][n4];
                unsigned long long b0 = pk2(wv4.x, wv4.y);
                unsigned long long b1 = pk2(wv4.z, wv4.w);
                float av[4];
                av[0] = (t == 0) ? a0.x : (t == 1) ? a0.y : (t == 2) ? a0.z : a0.w;
                av[1] = (t == 0) ? a1.x : (t == 1) ? a1.y : (t == 2) ? a1.z : a1.w;
                av[2] = (t == 0) ? a2.x : (t == 1) ? a2.y : (t == 2) ? a2.z : a2.w;
                av[3] = (t == 0) ? a3.x : (t == 1) ? a3.y : (t == 2) ? a3.z : a3.w;
#pragma unroll
                for (int j = 0; j < 4; j++) {
                    unsigned long long aa = pk2(av[j], av[j]);
                    fma2(acc[j][0], aa, b0);
                    fma2(acc[j][1], aa, b1);
                }
            }
        }
        __syncthreads();
    }

    float* dst = (mat == 0) ? g_q2 : (mat == 1) ? g_k2 : g_v2;
#pragma unroll
    for (int j = 0; j < 4; j++) {
        float2 c0 = upk2(acc[j][0]);
        float2 c1 = upk2(acc[j][1]);
        float4 v = make_float4(c0.x, c0.y, c1.x, c1.y);
        *(float4*)&dst[((size_t)(m0 + m4 + j) * NBO + kb) * DKQ + n4] = v;
    }
}

// =====================================================================
// K5: MHA attend + fc/gate + final hx_out combine.  One CTA per batch.
// =====================================================================
__global__ void __launch_bounds__(256) k5_mha(
    const float* __restrict__ hx,
    const float* __restrict__ fcw, const float* __restrict__ fcb,
    const float* __restrict__ gw,  const float* __restrict__ gb,
    float* __restrict__ hx_out)
{
    __shared__ float sq2[NBO][DKQ];
    __shared__ float sk2[NBO][DKQ];
    __shared__ float sv2[NBO][DKQ];
    __shared__ float sat[NBO][NBO];
    __shared__ float so2[NBO][DKQ];

    const int tid = threadIdx.x;
    const size_t b = blockIdx.x;

    for (int i = tid; i < NBO * DKQ; i += 256) {
        ((float*)sq2)[i] = g_q2[b * NBO * DKQ + i];
        ((float*)sk2)[i] = g_k2[b * NBO * DKQ + i];
        ((float*)sv2)[i] = g_v2[b * NBO * DKQ + i];
    }
    __syncthreads();

    if (tid < 64) {
        int kq = tid >> 3, kj = tid & 7;
        float s = 0.f;
        for (int e = 0; e < DKQ; e++) s += sq2[kq][e] * sk2[kj][e];
        sat[kq][kj] = s * 0.125f;
    }
    __syncthreads();
    if (tid < NBO) {
        float mx = -1e30f;
        for (int j = 0; j < NBO; j++) mx = fmaxf(mx, sat[tid][j]);
        float den = 0.f;
        for (int j = 0; j < NBO; j++) { float e = expf(sat[tid][j] - mx); sat[tid][j] = e; den += e; }
        float inv = 1.0f / den;
        for (int j = 0; j < NBO; j++) sat[tid][j] *= inv;
    }
    __syncthreads();
    for (int i = tid; i < NBO * DKQ; i += 256) {
        int k = i >> 6, e = i & 63;
        float a = 0.f;
        for (int j = 0; j < NBO; j++) a += sat[k][j] * sv2[j][e];
        so2[k][e] = a;
    }
    __syncthreads();

    const int d0 = tid * 2;
    float2 ao[NBO], ag[NBO];
#pragma unroll
    for (int k = 0; k < NBO; k++) { ao[k] = make_float2(0.f, 0.f); ag[k] = make_float2(0.f, 0.f); }

    for (int e = 0; e < DKQ; e++) {
        float2 fw  = *(const float2*)&fcw[(size_t)e * BSO + d0];
        float2 gwv = *(const float2*)&gw[(size_t)e * BSO + d0];
#pragma unroll
        for (int k = 0; k < NBO; k++) {
            float o = so2[k][e];
            ao[k].x += o * fw.x;  ao[k].y += o * fw.y;
            ag[k].x += o * gwv.x; ag[k].y += o * gwv.y;
        }
    }

    float fb0 = fcb[d0], fb1 = fcb[d0 + 1];
    float gb0 = gb[d0],  gb1 = gb[d0 + 1];
#pragma unroll
    for (int k = 0; k < NBO; k++) {
        float m = g_mblk[b * NBO + k];
        float hn0 = g_hnew[(b * NBO + k) * BSO + d0];
        float hn1 = g_hnew[(b * NBO + k) * BSO + d0 + 1];
        float v0 = hn0 + sigf(ag[k].x + gb0) * tanhf(ao[k].x + fb0);
        float v1 = hn1 + sigf(ag[k].y + gb1) * tanhf(ao[k].y + fb1);
        size_t idx = b * NHID + (size_t)k * BSO + d0;
        hx_out[idx]     = m * v0 + (1.0f - m) * hx[idx];
        hx_out[idx + 1] = m * v1 + (1.0f - m) * hx[idx + 1];
    }
}

// =====================================================================
extern "C" void kernel_launch(void* const* d_in, const int* in_sizes, int n_in,
                              void* d_out, int out_size) {
    const float* inp    = (const float*)d_in[0];
    const float* hx     = (const float*)d_in[1];
    const float* cx     = (const float*)d_in[2];
    const float* ia_wq  = (const float*)d_in[3];
    const float* ia_wk  = (const float*)d_in[4];
    const float* ia_wv  = (const float*)d_in[5];
    const float* ia_fcw = (const float*)d_in[6];
    const float* ia_fcb = (const float*)d_in[7];
    const float* mha_wq = (const float*)d_in[8];
    const float* mha_wk = (const float*)d_in[9];
    const float* mha_wv = (const float*)d_in[10];
    const float* mha_fcw= (const float*)d_in[11];
    const float* mha_fcb= (const float*)d_in[12];
    const float* mha_gw = (const float*)d_in[13];
    const float* mha_gb = (const float*)d_in[14];
    const float* w_ih   = (const float*)d_in[15];
    const float* w_hh   = (const float*)d_in[16];
    const float* b_ih   = (const float*)d_in[17];
    const float* b_hh   = (const float*)d_in[18];

    float* out   = (float*)d_out;
    const size_t N = (size_t)BSZ * NHID;
    float* out_hx   = out;
    float* out_cx   = out + N;
    float* out_mask = out + 2 * N;

    cudaFuncSetAttribute(k2m_gemm, cudaFuncAttributeMaxDynamicSharedMemorySize, K2_SMEM);

    k_pre<<<PRE_BLOCKS, 256>>>(inp, hx, ia_wq, ia_wk, ia_wv, ia_fcw, ia_fcb,
                               w_ih, w_hh, out_mask);
    k2m_gemm<<<dim3(GATES / 128, BSZ / 128, NBO), 256, K2_SMEM>>>();
    k3_lstm_ew<<<(unsigned)(((size_t)BSZ * NBO * BSO / 4 + 255) / 256), 256>>>(cx, b_ih, b_hh, out_cx);
    k4_qkv<<<dim3(3, BSZ / 64, NBO), 256>>>(mha_wq, mha_wk, mha_wv);
    k5_mha<<<BSZ, 256>>>(hx, mha_fcw, mha_fcb, mha_gw, mha_gb, out_hx);
}

// round 13
// speedup vs baseline: 1.0730x; 1.0271x over previous
#include <cuda_runtime.h>
#include <cuda_bf16.h>
#include <math.h>
#include <stdint.h>

#define BSZ   1024
#define NBIN  4
#define BSIN  128
#define NKEY  5
#define NBO   8
#define BSO   512
#define NHID  4096
#define DKQ   64
#define GATES 2048

// ------------- scratch (allocation-free: __device__ globals) -------------
__device__ float g_gates  [(size_t)BSZ * NBO * GATES];
__device__ float g_hnew   [(size_t)BSZ * NBO * BSO];
__device__ float g_q2     [(size_t)BSZ * NBO * DKQ];
__device__ float g_k2     [(size_t)BSZ * NBO * DKQ];
__device__ float g_v2     [(size_t)BSZ * NBO * DKQ];
__device__ float g_mblk   [(size_t)BSZ * NBO];
// bf16 hi/lo split operands for the tensor-core LSTM GEMM
__device__ __nv_bfloat16 g_ahi[(size_t)NBO * 1024 * 1024];
__device__ __nv_bfloat16 g_alo[(size_t)NBO * 1024 * 1024];
__device__ __nv_bfloat16 g_bhi[(size_t)NBO * 2048 * 1024];
__device__ __nv_bfloat16 g_blo[(size_t)NBO * 2048 * 1024];
// bf16 hi/lo split of h_new: [kb][m=1024][k=512]
__device__ __nv_bfloat16 g_h2hi[(size_t)NBO * 1024 * 512];
__device__ __nv_bfloat16 g_h2lo[(size_t)NBO * 1024 * 512];
// bf16 hi/lo split of mha wq/wk/wv transposed: [mat*8+kb][n=64][k=512]
__device__ __nv_bfloat16 g_wqhi[(size_t)3 * NBO * 64 * 512];
__device__ __nv_bfloat16 g_wqlo[(size_t)3 * NBO * 64 * 512];

__device__ __forceinline__ float sigf(float x) { return 1.0f / (1.0f + expf(-x)); }

// ------------- f32x2 packed FMA helpers -------------
__device__ __forceinline__ unsigned long long pk2(float x, float y) {
    unsigned long long r;
    asm("mov.b64 %0, {%1, %2};" : "=l"(r) : "f"(x), "f"(y));
    return r;
}
__device__ __forceinline__ void fma2(unsigned long long& d, unsigned long long a, unsigned long long b) {
    asm("fma.rn.f32x2 %0, %1, %2, %0;" : "+l"(d) : "l"(a), "l"(b));
}
__device__ __forceinline__ float2 upk2(unsigned long long v) {
    float2 f;
    asm("mov.b64 {%0, %1}, %2;" : "=f"(f.x), "=f"(f.y) : "l"(v));
    return f;
}

// ------------- mma.sync / ldmatrix / cp.async helpers -------------
__device__ __forceinline__ uint32_t smem_u32(const void* p) {
    uint32_t a;
    asm("{ .reg .u64 t; cvta.to.shared.u64 t, %1; cvt.u32.u64 %0, t; }" : "=r"(a) : "l"(p));
    return a;
}
__device__ __forceinline__ uint32_t swz64(uint32_t b) { return b ^ ((b >> 3) & 0x30); }

__device__ __forceinline__ void ldsm_x4(uint32_t addr, uint32_t* r) {
    asm volatile("ldmatrix.sync.aligned.m8n8.x4.shared.b16 {%0,%1,%2,%3}, [%4];"
                 : "=r"(r[0]), "=r"(r[1]), "=r"(r[2]), "=r"(r[3]) : "r"(addr));
}
__device__ __forceinline__ void mma_bf16(float* c, const uint32_t* a, uint32_t b0, uint32_t b1) {
    asm volatile("mma.sync.aligned.m16n8k16.row.col.f32.bf16.bf16.f32 "
                 "{%0,%1,%2,%3}, {%4,%5,%6,%7}, {%8,%9}, {%0,%1,%2,%3};"
                 : "+f"(c[0]), "+f"(c[1]), "+f"(c[2]), "+f"(c[3])
                 : "r"(a[0]), "r"(a[1]), "r"(a[2]), "r"(a[3]), "r"(b0), "r"(b1));
}
__device__ __forceinline__ void cpa16(uint32_t dst, const void* src) {
    asm volatile("cp.async.cg.shared.global [%0], [%1], 16;" :: "r"(dst), "l"(src));
}
__device__ __forceinline__ void cp_commit() { asm volatile("cp.async.commit_group;"); }
__device__ __forceinline__ void cp_wait1() { asm volatile("cp.async.wait_group 1;"); }
__device__ __forceinline__ void cp_wait0() { asm volatile("cp.async.wait_group 0;"); }

// =====================================================================
// K_PRE: fused (k1 input-attention | prep_b | prep_a2 | prep_wqkv).
// =====================================================================
#define K1_BPB 4
#define K1_BLOCKS   (BSZ / K1_BPB)                /* 256  */
#define PB_BLOCKS   (32 * 16 * 8)                 /* 4096 */
#define PA_BLOCKS   2048
#define PW_BLOCKS   (3 * 8 * 8)                   /* 192  */
#define PRE_BLOCKS  (K1_BLOCKS + PB_BLOCKS + PA_BLOCKS + PW_BLOCKS)

struct K1Smem {
    float sx[K1_BPB][NKEY * BSIN];
    float sk[K1_BPB][NKEY][DKQ];
    float sv[K1_BPB][NKEY][DKQ];
    float sq[K1_BPB][NBO][DKQ];
    float so[K1_BPB][NBO][DKQ];
    float sattn[K1_BPB][NBO][NKEY];
    float smb[K1_BPB][NBO];
};
union PreSmem {
    K1Smem k1;
    float ts[64][65];
};

__global__ void __launch_bounds__(256) k_pre(
    const float* __restrict__ inp, const float* __restrict__ hx,
    const float* __restrict__ wq, const float* __restrict__ wk, const float* __restrict__ wv,
    const float* __restrict__ fcw, const float* __restrict__ fcb,
    const float* __restrict__ w_ih, const float* __restrict__ w_hh,
    const float* __restrict__ mwq, const float* __restrict__ mwk, const float* __restrict__ mwv,
    float* __restrict__ mask_out)
{
    __shared__ PreSmem su;
    const int tid = threadIdx.x;
    const int bid = blockIdx.x;

    if (bid < K1_BLOCKS) {
        auto& sx = su.k1.sx;  auto& sk = su.k1.sk;  auto& sv = su.k1.sv;
        auto& sq = su.k1.sq;  auto& so = su.k1.so;
        auto& sattn = su.k1.sattn;  auto& smb = su.k1.smb;
        const int b0 = bid * K1_BPB;

        for (int i = tid; i < K1_BPB * NKEY * BSIN; i += 256) {
            int bi = i / (NKEY * BSIN);
            int j  = i % (NKEY * BSIN);
            sx[bi][j] = (j < NBIN * BSIN) ? inp[(size_t)(b0 + bi) * (NBIN * BSIN) + j] : 0.0f;
        }
        __syncthreads();

        if (tid < 128) {
            const int n  = tid >> 4;
            const int e4 = (tid & 15) * 4;
            const float* wp = wq + (size_t)(n * BSO) * DKQ + e4;
            float4 aq[K1_BPB];
#pragma unroll
            for (int bi = 0; bi < K1_BPB; bi++) aq[bi] = make_float4(0.f, 0.f, 0.f, 0.f);
#pragma unroll 4
            for (int d = 0; d < BSO; d++) {
                float4 w4 = *(const float4*)(wp + (size_t)d * DKQ);
#pragma unroll
                for (int bi = 0; bi < K1_BPB; bi++) {
                    float hv = __ldg(&hx[(size_t)(b0 + bi) * NHID + n * BSO + d]);
                    aq[bi].x += hv * w4.x; aq[bi].y += hv * w4.y;
                    aq[bi].z += hv * w4.z; aq[bi].w += hv * w4.w;
                }
            }
#pragma unroll
            for (int bi = 0; bi < K1_BPB; bi++) *(float4*)&sq[bi][n][e4] = aq[bi];
        } else if (tid < 128 + NKEY * 16) {
            const int g  = tid - 128;
            const int n  = g / 16;
            const int e4 = (g % 16) * 4;
            const float* wkp = wk + (size_t)(n * BSIN) * DKQ + e4;
            const float* wvp = wv + (size_t)(n * BSIN) * DKQ + e4;
            float4 ak[K1_BPB], av[K1_BPB];
#pragma unroll
            for (int bi = 0; bi < K1_BPB; bi++) {
                ak[bi] = make_float4(0.f, 0.f, 0.f, 0.f);
                av[bi] = make_float4(0.f, 0.f, 0.f, 0.f);
            }
#pragma unroll 4
            for (int d = 0; d < BSIN; d++) {
                float4 a4 = *(const float4*)(wkp + (size_t)d * DKQ);
                float4 b4 = *(const float4*)(wvp + (size_t)d * DKQ);
#pragma unroll
                for (int bi = 0; bi < K1_BPB; bi++) {
                    float xv = sx[bi][n * BSIN + d];
                    ak[bi].x += xv * a4.x; ak[bi].y += xv * a4.y;
                    ak[bi].z += xv * a4.z; ak[bi].w += xv * a4.w;
                    av[bi].x += xv * b4.x; av[bi].y += xv * b4.y;
                    av[bi].z += xv * b4.z; av[bi].w += xv * b4.w;
                }
            }
#pragma unroll
            for (int bi = 0; bi < K1_BPB; bi++) {
                *(float4*)&sk[bi][n][e4] = ak[bi];
                *(float4*)&sv[bi][n][e4] = av[bi];
            }
        }
        __syncthreads();

        if (tid < K1_BPB * NBO) {
            int bi = tid / NBO, n = tid % NBO;
            float s[NKEY];
            float mx = -1e30f;
            for (int j = 0; j < NKEY; j++) {
                float a = 0.f;
                for (int e = 0; e < DKQ; e++) a += sq[bi][n][e] * sk[bi][j][e];
                a *= 0.125f;
                s[j] = a;
                mx = fmaxf(mx, a);
            }
            float den = 0.f;
            for (int j = 0; j < NKEY; j++) { s[j] = expf(s[j] - mx); den += s[j]; }
            float inv = 1.0f / den;
            for (int j = 0; j < NKEY; j++) sattn[bi][n][j] = s[j] * inv;
        }
        __syncthreads();

        if (tid < K1_BPB) {
            int bi = tid;
            float sc[NBO], t[NBO];
            for (int n = 0; n < NBO; n++) { sc[n] = sattn[bi][n][0]; t[n] = sc[n]; }
            for (int a = 0; a < 4; a++) {
                int mi = a;
                for (int b = a + 1; b < NBO; b++) if (t[b] > t[mi]) mi = b;
                float tmp = t[a]; t[a] = t[mi]; t[mi] = tmp;
            }
            float thr = t[3] - 0.01f;
            for (int n = 0; n < NBO; n++) {
                float m = (sc[n] > thr) ? 1.0f : 0.0f;
                smb[bi][n] = m;
                g_mblk[(size_t)(b0 + bi) * NBO + n] = m;
            }
        }
        __syncthreads();

        for (int i = tid; i < K1_BPB * NBO * DKQ; i += 256) {
            int bi = i / (NBO * DKQ);
            int r  = i % (NBO * DKQ);
            int n  = r / DKQ;
            int e  = r % DKQ;
            float a = 0.f;
            for (int j = 0; j < NKEY; j++) a += sattn[bi][n][j] * sv[bi][j][e];
            so[bi][n][e] = a;
        }
        __syncthreads();

        for (int round = 0; round < 4; round++) {
            int g  = round * 256 + tid;
            int n  = g >> 7;
            int c4 = (g & 127) * 4;
            float4 bias = *(const float4*)&fcb[c4];
            float4 a[K1_BPB];
#pragma unroll
            for (int bi = 0; bi < K1_BPB; bi++) a[bi] = bias;
#pragma unroll 4
            for (int e = 0; e < DKQ; e++) {
                float4 w4 = *(const float4*)&fcw[(size_t)e * BSO + c4];
#pragma unroll
                for (int bi = 0; bi < K1_BPB; bi++) {
                    float s = so[bi][n][e];
                    a[bi].x += s * w4.x; a[bi].y += s * w4.y;
                    a[bi].z += s * w4.z; a[bi].w += s * w4.w;
                }
            }
#pragma unroll
            for (int bi = 0; bi < K1_BPB; bi++) {
                float xs[4] = {a[bi].x, a[bi].y, a[bi].z, a[bi].w};
                union { __nv_bfloat16 h[4]; uint2 u; } vh, vl;
#pragma unroll
                for (int j = 0; j < 4; j++) {
                    __nv_bfloat16 hi = __float2bfloat16(xs[j]);
                    vh.h[j] = hi;
                    vl.h[j] = __float2bfloat16(xs[j] - __bfloat162float(hi));
                }
                size_t ao = ((size_t)n * 1024 + (b0 + bi)) * 1024 + c4;
                *(uint2*)&g_ahi[ao] = vh.u;
                *(uint2*)&g_alo[ao] = vl.u;
                float m = smb[bi][n];
                *(float4*)&mask_out[(size_t)(b0 + bi) * NHID + n * BSO + c4] = make_float4(m, m, m, m);
            }
        }
    } else if (bid < K1_BLOCKS + PB_BLOCKS) {
        auto& ts = su.ts;
        const int pb = bid - K1_BLOCKS;
        const int n0 = (pb & 31) * 64;
        const int k0 = ((pb >> 5) & 15) * 64;
        const int kb = pb >> 9;

        const float* srcm = (k0 < 512) ? (w_ih + (size_t)kb * 512 * GATES)
                                       : (w_hh + (size_t)kb * 512 * GATES);
        const int krow0 = (k0 < 512) ? k0 : (k0 - 512);

#pragma unroll
        for (int p = 0; p < 16; p++) {
            int idx = p * 256 + tid;
            int r = idx >> 6;
            int c = idx & 63;
            ts[r][c] = srcm[(size_t)(krow0 + r) * GATES + n0 + c];
        }
        __syncthreads();

#pragma unroll
        for (int g = 0; g < 2; g++) {
            int n   = (tid >> 3) + g * 32;
            int kk0 = (tid & 7) * 8;
            union { __nv_bfloat16 h[8]; uint4 u; } vh, vl;
#pragma unroll
            for (int j = 0; j < 8; j++) {
                float x = ts[kk0 + j][n];
                __nv_bfloat16 hi = __float2bfloat16(x);
                vh.h[j] = hi;
                vl.h[j] = __float2bfloat16(x - __bfloat162float(hi));
            }
            size_t o = ((size_t)kb * GATES + n0 + n) * 1024 + k0 + kk0;
            *(uint4*)&g_bhi[o] = vh.u;
            *(uint4*)&g_blo[o] = vl.u;
        }
    } else if (bid < K1_BLOCKS + PB_BLOCKS + PA_BLOCKS) {
        size_t idx = (size_t)(bid - K1_BLOCKS - PB_BLOCKS) * 256 + tid;
        int k8 = (int)(idx & 63);
        int m  = (int)((idx >> 6) & 1023);
        int kb = (int)(idx >> 16);
        int k  = k8 * 8;

        const float* src = &hx[(size_t)m * NHID + kb * BSO + k];
        float4 a = *(const float4*)src;
        float4 b = *(const float4*)(src + 4);
        float xs[8] = {a.x, a.y, a.z, a.w, b.x, b.y, b.z, b.w};
        union { __nv_bfloat16 h[8]; uint4 u; } vh, vl;
#pragma unroll
        for (int j = 0; j < 8; j++) {
            __nv_bfloat16 hi = __float2bfloat16(xs[j]);
            vh.h[j] = hi;
            vl.h[j] = __float2bfloat16(xs[j] - __bfloat162float(hi));
        }
        size_t o = ((size_t)kb * 1024 + m) * 1024 + 512 + k;
        *(uint4*)&g_ahi[o] = vh.u;
        *(uint4*)&g_alo[o] = vl.u;
    } else {
        // ---- prep_wqkv: transpose + hi/lo split of mha wq/wk/wv ----
        auto& ts = su.ts;
        const int pw  = bid - K1_BLOCKS - PB_BLOCKS - PA_BLOCKS;
        const int mat = pw >> 6;
        const int kb  = (pw >> 3) & 7;
        const int kt  = pw & 7;
        const float* wsrc = ((mat == 0) ? mwq : (mat == 1) ? mwk : mwv)
                            + (size_t)kb * BSO * DKQ;

#pragma unroll
        for (int p = 0; p < 16; p++) {
            int idx = p * 256 + tid;
            int r = idx >> 6;
            int c = idx & 63;
            ts[r][c] = wsrc[(size_t)(kt * 64 + r) * DKQ + c];
        }
        __syncthreads();

#pragma unroll
        for (int g = 0; g < 2; g++) {
            int n   = (tid >> 3) + g * 32;
            int kk0 = (tid & 7) * 8;
            union { __nv_bfloat16 h[8]; uint4 u; } vh, vl;
#pragma unroll
            for (int j = 0; j < 8; j++) {
                float x = ts[kk0 + j][n];
                __nv_bfloat16 hi = __float2bfloat16(x);
                vh.h[j] = hi;
                vl.h[j] = __float2bfloat16(x - __bfloat162float(hi));
            }
            size_t o = ((size_t)(mat * 8 + kb) * 64 + n) * 512 + kt * 64 + kk0;
            *(uint4*)&g_wqhi[o] = vh.u;
            *(uint4*)&g_wqlo[o] = vl.u;
        }
    }
}

// =====================================================================
// K2M: LSTM gate GEMM (mma.sync bf16, hi/lo 3 passes), proven config.
// =====================================================================
#define K2_STG   32768
#define K2_SMEM  (3 * K2_STG)
#define OFF_AH   0
#define OFF_AL   8192
#define OFF_BH   16384
#define OFF_BL   24576

__global__ void __launch_bounds__(256, 2) k2m_gemm()
{
    extern __shared__ char smem[];
    const int tid = threadIdx.x;
    const int wid = tid >> 5;
    const int lid = tid & 31;
    const uint32_t sbase = smem_u32(smem);
    const int nb = blockIdx.x * 128;
    const int mb = blockIdx.y * 128;
    const int kb = blockIdx.z;

    const __nv_bfloat16* Ah = g_ahi + ((size_t)kb * 1024 + mb) * 1024;
    const __nv_bfloat16* Al = g_alo + ((size_t)kb * 1024 + mb) * 1024;
    const __nv_bfloat16* Bh = g_bhi + ((size_t)kb * 2048 + nb) * 1024;
    const __nv_bfloat16* Bl = g_blo + ((size_t)kb * 2048 + nb) * 1024;

    const int mw = (wid >> 2) * 64;
    const int nw = (wid & 3) * 32;
    const int g  = lid >> 3;
    const int r  = lid & 7;

    uint32_t offA[4][2], offB[2][2];
#pragma unroll
    for (int i = 0; i < 4; i++)
#pragma unroll
        for (int ks = 0; ks < 2; ks++) {
            int m = mw + i * 16 + (g & 1) * 8 + r;
            int k = ks * 16 + (g >> 1) * 8;
            offA[i][ks] = swz64((uint32_t)(m * 64 + k * 2));
        }
#pragma unroll
    for (int j = 0; j < 2; j++)
#pragma unroll
        for (int ks = 0; ks < 2; ks++) {
            int n = nw + j * 16 + (g & 1) * 8 + r;
            int k = ks * 16 + (g >> 1) * 8;
            offB[j][ks] = swz64((uint32_t)(n * 64 + k * 2));
        }

    float acc[4][4][4];
#pragma unroll
    for (int i = 0; i < 4; i++)
#pragma unroll
        for (int j = 0; j < 4; j++)
#pragma unroll
            for (int c = 0; c < 4; c++) acc[i][j][c] = 0.f;

    const int c_row0 = tid >> 2;
    const int c_sl   = tid & 3;
    const uint32_t c_d0 = swz64((uint32_t)(c_row0 * 64 + c_sl * 16));
    const uint32_t c_d1 = swz64((uint32_t)((c_row0 + 64) * 64 + c_sl * 16));
    const size_t  c_g0 = (size_t)c_row0 * 1024 + c_sl * 8;
    const size_t  c_g1 = (size_t)(c_row0 + 64) * 1024 + c_sl * 8;

#pragma unroll
    for (int pc = 0; pc < 2; pc++) {
        uint32_t sb = sbase + pc * K2_STG;
        int kc = pc * 32;
        cpa16(sb + OFF_AH + c_d0, Ah + c_g0 + kc);
        cpa16(sb + OFF_AL + c_d0, Al + c_g0 + kc);
        cpa16(sb + OFF_BH + c_d0, Bh + c_g0 + kc);
        cpa16(sb + OFF_BL + c_d0, Bl + c_g0 + kc);
        cpa16(sb + OFF_AH + c_d1, Ah + c_g1 + kc);
        cpa16(sb + OFF_AL + c_d1, Al + c_g1 + kc);
        cpa16(sb + OFF_BH + c_d1, Bh + c_g1 + kc);
        cpa16(sb + OFF_BL + c_d1, Bl + c_g1 + kc);
        cp_commit();
    }

    int stage = 0;
    int pstage = 2;
    for (int ch = 0; ch < 32; ch++) {
        if (ch + 1 < 32) cp_wait1(); else cp_wait0();
        __syncthreads();

        if (ch + 2 < 32) {
            uint32_t sb = sbase + pstage * K2_STG;
            int kc = (ch + 2) * 32;
            cpa16(sb + OFF_AH + c_d0, Ah + c_g0 + kc);
            cpa16(sb + OFF_AL + c_d0, Al + c_g0 + kc);
            cpa16(sb + OFF_BH + c_d0, Bh + c_g0 + kc);
            cpa16(sb + OFF_BL + c_d0, Bl + c_g0 + kc);
            cpa16(sb + OFF_AH + c_d1, Ah + c_g1 + kc);
            cpa16(sb + OFF_AL + c_d1, Al + c_g1 + kc);
            cpa16(sb + OFF_BH + c_d1, Bh + c_g1 + kc);
            cpa16(sb + OFF_BL + c_d1, Bl + c_g1 + kc);
            cp_commit();
        }

        uint32_t sb = sbase + stage * K2_STG;
#pragma unroll
        for (int ks = 0; ks < 2; ks++) {
            uint32_t bh[2][4], bl[2][4];
#pragma unroll
            for (int j = 0; j < 2; j++) {
                ldsm_x4(sb + OFF_BH + offB[j][ks], bh[j]);
                ldsm_x4(sb + OFF_BL + offB[j][ks], bl[j]);
            }
#pragma unroll
            for (int i = 0; i < 4; i++) {
                uint32_t ah[4], al[4];
                ldsm_x4(sb + OFF_AH + offA[i][ks], ah);
                ldsm_x4(sb + OFF_AL + offA[i][ks], al);
#pragma unroll
                for (int jn = 0; jn < 4; jn++) {
                    const int jj = jn >> 1;
                    const int ss = jn & 1;
                    mma_bf16(acc[i][jn], ah, bh[jj][ss], bh[jj][ss + 2]);
                    mma_bf16(acc[i][jn], ah, bl[jj][ss], bl[jj][ss + 2]);
                    mma_bf16(acc[i][jn], al, bh[jj][ss], bh[jj][ss + 2]);
                }
            }
        }
        stage  = (stage == 2) ? 0 : stage + 1;
        pstage = (pstage == 2) ? 0 : pstage + 1;
    }

    const int rowc = lid >> 2;
    const int colc = (lid & 3) * 2;
#pragma unroll
    for (int i = 0; i < 4; i++) {
        int m0 = mb + mw + i * 16 + rowc;
#pragma unroll
        for (int jn = 0; jn < 4; jn++) {
            int n0 = nb + nw + jn * 8 + colc;
            *(float2*)&g_gates[((size_t)m0 * NBO + kb) * GATES + n0] =
                make_float2(acc[i][jn][0], acc[i][jn][1]);
            *(float2*)&g_gates[((size_t)(m0 + 8) * NBO + kb) * GATES + n0] =
                make_float2(acc[i][jn][2], acc[i][jn][3]);
        }
    }
}

// =====================================================================
// K3: LSTM elementwise, float4-vectorized; also emits h_new bf16 hi/lo.
// =====================================================================
__global__ void __launch_bounds__(256) k3_lstm_ew(
    const float* __restrict__ cx, const float* __restrict__ b_ih,
    const float* __restrict__ b_hh, float* __restrict__ cx_out)
{
    size_t i4 = (size_t)blockIdx.x * blockDim.x + threadIdx.x;
    size_t bk = i4 >> 7;
    int kb = (int)(bk & 7);
    int d  = (int)(i4 & 127) * 4;
    const float* g  = &g_gates[bk * GATES];
    const float* bi = &b_ih[(size_t)kb * GATES];
    const float* bh = &b_hh[(size_t)kb * GATES];

    float4 gi = *(const float4*)&g[d];
    float4 gf = *(const float4*)&g[d + 512];
    float4 gg = *(const float4*)&g[d + 1024];
    float4 go = *(const float4*)&g[d + 1536];
    float4 bi_i = *(const float4*)&bi[d],        bh_i = *(const float4*)&bh[d];
    float4 bi_f = *(const float4*)&bi[d + 512],  bh_f = *(const float4*)&bh[d + 512];
    float4 bi_g = *(const float4*)&bi[d + 1024], bh_g = *(const float4*)&bh[d + 1024];
    float4 bi_o = *(const float4*)&bi[d + 1536], bh_o = *(const float4*)&bh[d + 1536];
    float4 cb = *(const float4*)&cx[bk * BSO + d];
    float m = g_mblk[bk];

    float hn[4], co[4];
    float giv[4] = {gi.x, gi.y, gi.z, gi.w};
    float gfv[4] = {gf.x, gf.y, gf.z, gf.w};
    float ggv[4] = {gg.x, gg.y, gg.z, gg.w};
    float gov[4] = {go.x, go.y, go.z, go.w};
    float biiv[4] = {bi_i.x, bi_i.y, bi_i.z, bi_i.w};
    float bhiv[4] = {bh_i.x, bh_i.y, bh_i.z, bh_i.w};
    float bifv[4] = {bi_f.x, bi_f.y, bi_f.z, bi_f.w};
    float bhfv[4] = {bh_f.x, bh_f.y, bh_f.z, bh_f.w};
    float bigv[4] = {bi_g.x, bi_g.y, bi_g.z, bi_g.w};
    float bhgv[4] = {bh_g.x, bh_g.y, bh_g.z, bh_g.w};
    float biov[4] = {bi_o.x, bi_o.y, bi_o.z, bi_o.w};
    float bhov[4] = {bh_o.x, bh_o.y, bh_o.z, bh_o.w};
    float cbv[4] = {cb.x, cb.y, cb.z, cb.w};
#pragma unroll
    for (int j = 0; j < 4; j++) {
        float ig = sigf(giv[j] + biiv[j] + bhiv[j]);
        float fg = sigf(gfv[j] + bifv[j] + bhfv[j]);
        float gt = tanhf(ggv[j] + bigv[j] + bhgv[j]);
        float og = sigf(gov[j] + biov[j] + bhov[j]);
        float cn = fg * cbv[j] + ig * gt;
        hn[j] = og * tanhf(cn);
        co[j] = m * cn + (1.0f - m) * cbv[j];
    }
    *(float4*)&g_hnew[bk * BSO + d]  = make_float4(hn[0], hn[1], hn[2], hn[3]);
    *(float4*)&cx_out[bk * BSO + d] = make_float4(co[0], co[1], co[2], co[3]);

    // bf16 hi/lo split for the tensor-core qkv GEMM: [kb][b][d]
    union { __nv_bfloat16 h[4]; uint2 u; } vh, vl;
#pragma unroll
    for (int j = 0; j < 4; j++) {
        __nv_bfloat16 hi = __float2bfloat16(hn[j]);
        vh.h[j] = hi;
        vl.h[j] = __float2bfloat16(hn[j] - __bfloat162float(hi));
    }
    size_t ho = ((size_t)kb * 1024 + (bk >> 3)) * 512 + d;
    *(uint2*)&g_h2hi[ho] = vh.u;
    *(uint2*)&g_h2lo[ho] = vl.u;
}

// =====================================================================
// K4M: q2/k2/v2 GEMMs on mma.sync bf16 (hi/lo 3 passes).
//   CTA tile M=128, N=64, K=512 in 16 chunks of 32; double buffer.
//   8 warps = 4m x 2n, warp tile 32x32.  grid (3, 8, 8).
// =====================================================================
#define K4_STG   24576
#define K4_SMEM  (2 * K4_STG)      /* 49152 */
#define K4_AH    0
#define K4_AL    8192
#define K4_BH    16384
#define K4_BL    20480

__global__ void __launch_bounds__(256) k4m_qkv()
{
    extern __shared__ char smem[];
    const int tid = threadIdx.x;
    const int wid = tid >> 5;
    const int lid = tid & 31;
    const uint32_t sbase = smem_u32(smem);
    const int mat = blockIdx.x;
    const int mb  = blockIdx.y * 128;
    const int kb  = blockIdx.z;

    const __nv_bfloat16* Ah = g_h2hi + ((size_t)kb * 1024 + mb) * 512;
    const __nv_bfloat16* Al = g_h2lo + ((size_t)kb * 1024 + mb) * 512;
    const __nv_bfloat16* Bh = g_wqhi + (size_t)(mat * 8 + kb) * 64 * 512;
    const __nv_bfloat16* Bl = g_wqlo + (size_t)(mat * 8 + kb) * 64 * 512;

    const int mw = (wid >> 1) * 32;
    const int nw = (wid & 1) * 32;
    const int g  = lid >> 3;
    const int r  = lid & 7;

    uint32_t offA[2][2], offB[2][2];
#pragma unroll
    for (int i = 0; i < 2; i++)
#pragma unroll
        for (int ks = 0; ks < 2; ks++) {
            int m = mw + i * 16 + (g & 1) * 8 + r;
            int k = ks * 16 + (g >> 1) * 8;
            offA[i][ks] = swz64((uint32_t)(m * 64 + k * 2));
        }
#pragma unroll
    for (int j = 0; j < 2; j++)
#pragma unroll
        for (int ks = 0; ks < 2; ks++) {
            int n = nw + j * 16 + (g & 1) * 8 + r;
            int k = ks * 16 + (g >> 1) * 8;
            offB[j][ks] = swz64((uint32_t)(n * 64 + k * 2));
        }

    float acc[2][4][4];
#pragma unroll
    for (int i = 0; i < 2; i++)
#pragma unroll
        for (int j = 0; j < 4; j++)
#pragma unroll
            for (int c = 0; c < 4; c++) acc[i][j][c] = 0.f;

    // cp.async thread mapping: A rows 0..127 (2 per thread), B rows 0..63
    const int a_row = tid >> 2;
    const int a_sl  = tid & 3;
    const uint32_t a_d0 = swz64((uint32_t)(a_row * 64 + a_sl * 16));
    const uint32_t a_d1 = swz64((uint32_t)((a_row + 64) * 64 + a_sl * 16));
    const size_t  a_g0 = (size_t)a_row * 512 + a_sl * 8;
    const size_t  a_g1 = (size_t)(a_row + 64) * 512 + a_sl * 8;
    const uint32_t b_d  = swz64((uint32_t)(a_row * 64 + a_sl * 16));   // rows 0..63
    const size_t  b_g  = (size_t)a_row * 512 + a_sl * 8;
    const bool b_act = (a_row < 64);

    // prologue: chunk 0 into stage 0
    {
        uint32_t sb = sbase;
        cpa16(sb + K4_AH + a_d0, Ah + a_g0);
        cpa16(sb + K4_AL + a_d0, Al + a_g0);
        cpa16(sb + K4_AH + a_d1, Ah + a_g1);
        cpa16(sb + K4_AL + a_d1, Al + a_g1);
        if (b_act) {
            cpa16(sb + K4_BH + b_d, Bh + b_g);
            cpa16(sb + K4_BL + b_d, Bl + b_g);
        }
        cp_commit();
    }

    for (int ch = 0; ch < 16; ch++) {
        if (ch + 1 < 16) {
            uint32_t sb = sbase + ((ch + 1) & 1) * K4_STG;
            int kc = (ch + 1) * 32;
            cpa16(sb + K4_AH + a_d0, Ah + a_g0 + kc);
            cpa16(sb + K4_AL + a_d0, Al + a_g0 + kc);
            cpa16(sb + K4_AH + a_d1, Ah + a_g1 + kc);
            cpa16(sb + K4_AL + a_d1, Al + a_g1 + kc);
            if (b_act) {
                cpa16(sb + K4_BH + b_d, Bh + b_g + kc);
                cpa16(sb + K4_BL + b_d, Bl + b_g + kc);
            }
            cp_commit();
            cp_wait1();
        } else {
            cp_wait0();
        }
        __syncthreads();

        uint32_t sb = sbase + (ch & 1) * K4_STG;
#pragma unroll
        for (int ks = 0; ks < 2; ks++) {
            uint32_t bh[2][4], bl[2][4];
#pragma unroll
            for (int j = 0; j < 2; j++) {
                ldsm_x4(sb + K4_BH + offB[j][ks], bh[j]);
                ldsm_x4(sb + K4_BL + offB[j][ks], bl[j]);
            }
#pragma unroll
            for (int i = 0; i < 2; i++) {
                uint32_t ah[4], al[4];
                ldsm_x4(sb + K4_AH + offA[i][ks], ah);
                ldsm_x4(sb + K4_AL + offA[i][ks], al);
#pragma unroll
                for (int jn = 0; jn < 4; jn++) {
                    const int jj = jn >> 1;
                    const int ss = jn & 1;
                    mma_bf16(acc[i][jn], ah, bh[jj][ss], bh[jj][ss + 2]);
                    mma_bf16(acc[i][jn], ah, bl[jj][ss], bl[jj][ss + 2]);
                    mma_bf16(acc[i][jn], al, bh[jj][ss], bh[jj][ss + 2]);
                }
            }
        }
        __syncthreads();
    }

    float* dst = (mat == 0) ? g_q2 : (mat == 1) ? g_k2 : g_v2;
    const int rowc = lid >> 2;
    const int colc = (lid & 3) * 2;
#pragma unroll
    for (int i = 0; i < 2; i++) {
        int m0 = mb + mw + i * 16 + rowc;
#pragma unroll
        for (int jn = 0; jn < 4; jn++) {
            int n0 = nw + jn * 8 + colc;
            *(float2*)&dst[((size_t)m0 * NBO + kb) * DKQ + n0] =
                make_float2(acc[i][jn][0], acc[i][jn][1]);
            *(float2*)&dst[((size_t)(m0 + 8) * NBO + kb) * DKQ + n0] =
                make_float2(acc[i][jn][2], acc[i][jn][3]);
        }
    }
}

// =====================================================================
// K5: MHA attend + fc/gate + final hx_out combine.  One CTA per batch.
// =====================================================================
__global__ void __launch_bounds__(256) k5_mha(
    const float* __restrict__ hx,
    const float* __restrict__ fcw, const float* __restrict__ fcb,
    const float* __restrict__ gw,  const float* __restrict__ gb,
    float* __restrict__ hx_out)
{
    __shared__ float sq2[NBO][DKQ];
    __shared__ float sk2[NBO][DKQ];
    __shared__ float sv2[NBO][DKQ];
    __shared__ float sat[NBO][NBO];
    __shared__ float so2[NBO][DKQ];

    const int tid = threadIdx.x;
    const size_t b = blockIdx.x;

    for (int i = tid; i < NBO * DKQ; i += 256) {
        ((float*)sq2)[i] = g_q2[b * NBO * DKQ + i];
        ((float*)sk2)[i] = g_k2[b * NBO * DKQ + i];
        ((float*)sv2)[i] = g_v2[b * NBO * DKQ + i];
    }
    __syncthreads();

    if (tid < 64) {
        int kq = tid >> 3, kj = tid & 7;
        float s = 0.f;
        for (int e = 0; e < DKQ; e++) s += sq2[kq][e] * sk2[kj][e];
        sat[kq][kj] = s * 0.125f;
    }
    __syncthreads();
    if (tid < NBO) {
        float mx = -1e30f;
        for (int j = 0; j < NBO; j++) mx = fmaxf(mx, sat[tid][j]);
        float den = 0.f;
        for (int j = 0; j < NBO; j++) { float e = expf(sat[tid][j] - mx); sat[tid][j] = e; den += e; }
        float inv = 1.0f / den;
        for (int j = 0; j < NBO; j++) sat[tid][j] *= inv;
    }
    __syncthreads();
    for (int i = tid; i < NBO * DKQ; i += 256) {
        int k = i >> 6, e = i & 63;
        float a = 0.f;
        for (int j = 0; j < NBO; j++) a += sat[k][j] * sv2[j][e];
        so2[k][e] = a;
    }
    __syncthreads();

    const int d0 = tid * 2;
    float2 ao[NBO], ag[NBO];
#pragma unroll
    for (int k = 0; k < NBO; k++) { ao[k] = make_float2(0.f, 0.f); ag[k] = make_float2(0.f, 0.f); }

    for (int e = 0; e < DKQ; e++) {
        float2 fw  = *(const float2*)&fcw[(size_t)e * BSO + d0];
        float2 gwv = *(const float2*)&gw[(size_t)e * BSO + d0];
#pragma unroll
        for (int k = 0; k < NBO; k++) {
            float o = so2[k][e];
            ao[k].x += o * fw.x;  ao[k].y += o * fw.y;
            ag[k].x += o * gwv.x; ag[k].y += o * gwv.y;
        }
    }

    float fb0 = fcb[d0], fb1 = fcb[d0 + 1];
    float gb0 = gb[d0],  gb1 = gb[d0 + 1];
#pragma unroll
    for (int k = 0; k < NBO; k++) {
        float m = g_mblk[b * NBO + k];
        float hn0 = g_hnew[(b * NBO + k) * BSO + d0];
        float hn1 = g_hnew[(b * NBO + k) * BSO + d0 + 1];
        float v0 = hn0 + sigf(ag[k].x + gb0) * tanhf(ao[k].x + fb0);
        float v1 = hn1 + sigf(ag[k].y + gb1) * tanhf(ao[k].y + fb1);
        size_t idx = b * NHID + (size_t)k * BSO + d0;
        hx_out[idx]     = m * v0 + (1.0f - m) * hx[idx];
        hx_out[idx + 1] = m * v1 + (1.0f - m) * hx[idx + 1];
    }
}

// =====================================================================
extern "C" void kernel_launch(void* const* d_in, const int* in_sizes, int n_in,
                              void* d_out, int out_size) {
    const float* inp    = (const float*)d_in[0];
    const float* hx     = (const float*)d_in[1];
    const float* cx     = (const float*)d_in[2];
    const float* ia_wq  = (const float*)d_in[3];
    const float* ia_wk  = (const float*)d_in[4];
    const float* ia_wv  = (const float*)d_in[5];
    const float* ia_fcw = (const float*)d_in[6];
    const float* ia_fcb = (const float*)d_in[7];
    const float* mha_wq = (const float*)d_in[8];
    const float* mha_wk = (const float*)d_in[9];
    const float* mha_wv = (const float*)d_in[10];
    const float* mha_fcw= (const float*)d_in[11];
    const float* mha_fcb= (const float*)d_in[12];
    const float* mha_gw = (const float*)d_in[13];
    const float* mha_gb = (const float*)d_in[14];
    const float* w_ih   = (const float*)d_in[15];
    const float* w_hh   = (const float*)d_in[16];
    const float* b_ih   = (const float*)d_in[17];
    const float* b_hh   = (const float*)d_in[18];

    float* out   = (float*)d_out;
    const size_t N = (size_t)BSZ * NHID;
    float* out_hx   = out;
    float* out_cx   = out + N;
    float* out_mask = out + 2 * N;

    cudaFuncSetAttribute(k2m_gemm, cudaFuncAttributeMaxDynamicSharedMemorySize, K2_SMEM);
    cudaFuncSetAttribute(k4m_qkv, cudaFuncAttributeMaxDynamicSharedMemorySize, K4_SMEM);

    k_pre<<<PRE_BLOCKS, 256>>>(inp, hx, ia_wq, ia_wk, ia_wv, ia_fcw, ia_fcb,
                               w_ih, w_hh, mha_wq, mha_wk, mha_wv, out_mask);
    k2m_gemm<<<dim3(GATES / 128, BSZ / 128, NBO), 256, K2_SMEM>>>();
    k3_lstm_ew<<<(unsigned)(((size_t)BSZ * NBO * BSO / 4 + 255) / 256), 256>>>(cx, b_ih, b_hh, out_cx);
    k4m_qkv<<<dim3(3, BSZ / 128, NBO), 256, K4_SMEM>>>();
    k5_mha<<<BSZ, 256>>>(hx, mha_fcw, mha_fcb, mha_gw, mha_gb, out_hx);
}

// round 14
// speedup vs baseline: 1.0905x; 1.0164x over previous
#include <cuda_runtime.h>
#include <cuda_bf16.h>
#include <math.h>
#include <stdint.h>

#define BSZ   1024
#define NBIN  4
#define BSIN  128
#define NKEY  5
#define NBO   8
#define BSO   512
#define NHID  4096
#define DKQ   64
#define GATES 2048

// ------------- scratch (allocation-free: __device__ globals) -------------
__device__ float g_gates  [(size_t)BSZ * NBO * GATES];
__device__ float g_hnew   [(size_t)BSZ * NBO * BSO];
__device__ float g_q2     [(size_t)BSZ * NBO * DKQ];
__device__ float g_k2     [(size_t)BSZ * NBO * DKQ];
__device__ float g_v2     [(size_t)BSZ * NBO * DKQ];
__device__ float g_mblk   [(size_t)BSZ * NBO];
// bf16 hi/lo split operands for the tensor-core LSTM GEMM
__device__ __nv_bfloat16 g_ahi[(size_t)NBO * 1024 * 1024];
__device__ __nv_bfloat16 g_alo[(size_t)NBO * 1024 * 1024];
__device__ __nv_bfloat16 g_bhi[(size_t)NBO * 2048 * 1024];
__device__ __nv_bfloat16 g_blo[(size_t)NBO * 2048 * 1024];
// bf16 hi/lo split of h_new: [kb][m=1024][k=512]
__device__ __nv_bfloat16 g_h2hi[(size_t)NBO * 1024 * 512];
__device__ __nv_bfloat16 g_h2lo[(size_t)NBO * 1024 * 512];
// bf16 hi/lo split of mha wq/wk/wv transposed: [mat*8+kb][n=64][k=512]
__device__ __nv_bfloat16 g_wqhi[(size_t)3 * NBO * 64 * 512];
__device__ __nv_bfloat16 g_wqlo[(size_t)3 * NBO * 64 * 512];

__device__ __forceinline__ float sigf(float x) { return 1.0f / (1.0f + expf(-x)); }

// ------------- f32x2 packed FMA helpers -------------
__device__ __forceinline__ unsigned long long pk2(float x, float y) {
    unsigned long long r;
    asm("mov.b64 %0, {%1, %2};" : "=l"(r) : "f"(x), "f"(y));
    return r;
}
__device__ __forceinline__ void fma2(unsigned long long& d, unsigned long long a, unsigned long long b) {
    asm("fma.rn.f32x2 %0, %1, %2, %0;" : "+l"(d) : "l"(a), "l"(b));
}
__device__ __forceinline__ float2 upk2(unsigned long long v) {
    float2 f;
    asm("mov.b64 {%0, %1}, %2;" : "=f"(f.x), "=f"(f.y) : "l"(v));
    return f;
}

// ------------- mma.sync / ldmatrix / cp.async helpers -------------
__device__ __forceinline__ uint32_t smem_u32(const void* p) {
    uint32_t a;
    asm("{ .reg .u64 t; cvta.to.shared.u64 t, %1; cvt.u32.u64 %0, t; }" : "=r"(a) : "l"(p));
    return a;
}
__device__ __forceinline__ uint32_t swz64(uint32_t b) { return b ^ ((b >> 3) & 0x30); }

__device__ __forceinline__ void ldsm_x4(uint32_t addr, uint32_t* r) {
    asm volatile("ldmatrix.sync.aligned.m8n8.x4.shared.b16 {%0,%1,%2,%3}, [%4];"
                 : "=r"(r[0]), "=r"(r[1]), "=r"(r[2]), "=r"(r[3]) : "r"(addr));
}
__device__ __forceinline__ void mma_bf16(float* c, const uint32_t* a, uint32_t b0, uint32_t b1) {
    asm volatile("mma.sync.aligned.m16n8k16.row.col.f32.bf16.bf16.f32 "
                 "{%0,%1,%2,%3}, {%4,%5,%6,%7}, {%8,%9}, {%0,%1,%2,%3};"
                 : "+f"(c[0]), "+f"(c[1]), "+f"(c[2]), "+f"(c[3])
                 : "r"(a[0]), "r"(a[1]), "r"(a[2]), "r"(a[3]), "r"(b0), "r"(b1));
}
__device__ __forceinline__ void cpa16(uint32_t dst, const void* src) {
    asm volatile("cp.async.cg.shared.global [%0], [%1], 16;" :: "r"(dst), "l"(src));
}
__device__ __forceinline__ void cp_commit() { asm volatile("cp.async.commit_group;"); }
__device__ __forceinline__ void cp_wait1() { asm volatile("cp.async.wait_group 1;"); }
__device__ __forceinline__ void cp_wait0() { asm volatile("cp.async.wait_group 0;"); }

// =====================================================================
// K_PRE: fused (k1 input-attention | prep_b | prep_a2 | prep_wqkv).
// =====================================================================
#define K1_BPB 4
#define K1_BLOCKS   (BSZ / K1_BPB)                /* 256  */
#define PB_BLOCKS   (32 * 16 * 8)                 /* 4096 */
#define PA_BLOCKS   2048
#define PW_BLOCKS   (3 * 8 * 8)                   /* 192  */
#define PRE_BLOCKS  (K1_BLOCKS + PB_BLOCKS + PA_BLOCKS + PW_BLOCKS)

struct K1Smem {
    float sx[K1_BPB][NKEY * BSIN];
    float sk[K1_BPB][NKEY][DKQ];
    float sv[K1_BPB][NKEY][DKQ];
    float sq[K1_BPB][NBO][DKQ];
    float so[K1_BPB][NBO][DKQ];
    float sattn[K1_BPB][NBO][NKEY];
    float smb[K1_BPB][NBO];
};
union PreSmem {
    K1Smem k1;
    float ts[64][65];
};

__global__ void __launch_bounds__(256) k_pre(
    const float* __restrict__ inp, const float* __restrict__ hx,
    const float* __restrict__ wq, const float* __restrict__ wk, const float* __restrict__ wv,
    const float* __restrict__ fcw, const float* __restrict__ fcb,
    const float* __restrict__ w_ih, const float* __restrict__ w_hh,
    const float* __restrict__ mwq, const float* __restrict__ mwk, const float* __restrict__ mwv,
    float* __restrict__ mask_out)
{
    __shared__ PreSmem su;
    const int tid = threadIdx.x;
    const int bid = blockIdx.x;

    if (bid < K1_BLOCKS) {
        auto& sx = su.k1.sx;  auto& sk = su.k1.sk;  auto& sv = su.k1.sv;
        auto& sq = su.k1.sq;  auto& so = su.k1.so;
        auto& sattn = su.k1.sattn;  auto& smb = su.k1.smb;
        const int b0 = bid * K1_BPB;

        for (int i = tid; i < K1_BPB * NKEY * BSIN; i += 256) {
            int bi = i / (NKEY * BSIN);
            int j  = i % (NKEY * BSIN);
            sx[bi][j] = (j < NBIN * BSIN) ? inp[(size_t)(b0 + bi) * (NBIN * BSIN) + j] : 0.0f;
        }
        __syncthreads();

        if (tid < 128) {
            const int n  = tid >> 4;
            const int e4 = (tid & 15) * 4;
            const float* wp = wq + (size_t)(n * BSO) * DKQ + e4;
            float4 aq[K1_BPB];
#pragma unroll
            for (int bi = 0; bi < K1_BPB; bi++) aq[bi] = make_float4(0.f, 0.f, 0.f, 0.f);
            for (int d = 0; d < BSO; d += 4) {
                float4 hv4[K1_BPB];
#pragma unroll
                for (int bi = 0; bi < K1_BPB; bi++)
                    hv4[bi] = *(const float4*)&hx[(size_t)(b0 + bi) * NHID + n * BSO + d];
#pragma unroll
                for (int dd = 0; dd < 4; dd++) {
                    float4 w4 = *(const float4*)(wp + (size_t)(d + dd) * DKQ);
#pragma unroll
                    for (int bi = 0; bi < K1_BPB; bi++) {
                        float hv = (dd == 0) ? hv4[bi].x : (dd == 1) ? hv4[bi].y
                                 : (dd == 2) ? hv4[bi].z : hv4[bi].w;
                        aq[bi].x += hv * w4.x; aq[bi].y += hv * w4.y;
                        aq[bi].z += hv * w4.z; aq[bi].w += hv * w4.w;
                    }
                }
            }
#pragma unroll
            for (int bi = 0; bi < K1_BPB; bi++) *(float4*)&sq[bi][n][e4] = aq[bi];
        } else if (tid < 128 + NKEY * 16) {
            const int g  = tid - 128;
            const int n  = g / 16;
            const int e4 = (g % 16) * 4;
            const float* wkp = wk + (size_t)(n * BSIN) * DKQ + e4;
            const float* wvp = wv + (size_t)(n * BSIN) * DKQ + e4;
            float4 ak[K1_BPB], av[K1_BPB];
#pragma unroll
            for (int bi = 0; bi < K1_BPB; bi++) {
                ak[bi] = make_float4(0.f, 0.f, 0.f, 0.f);
                av[bi] = make_float4(0.f, 0.f, 0.f, 0.f);
            }
#pragma unroll 4
            for (int d = 0; d < BSIN; d++) {
                float4 a4 = *(const float4*)(wkp + (size_t)d * DKQ);
                float4 b4 = *(const float4*)(wvp + (size_t)d * DKQ);
#pragma unroll
                for (int bi = 0; bi < K1_BPB; bi++) {
                    float xv = sx[bi][n * BSIN + d];
                    ak[bi].x += xv * a4.x; ak[bi].y += xv * a4.y;
                    ak[bi].z += xv * a4.z; ak[bi].w += xv * a4.w;
                    av[bi].x += xv * b4.x; av[bi].y += xv * b4.y;
                    av[bi].z += xv * b4.z; av[bi].w += xv * b4.w;
                }
            }
#pragma unroll
            for (int bi = 0; bi < K1_BPB; bi++) {
                *(float4*)&sk[bi][n][e4] = ak[bi];
                *(float4*)&sv[bi][n][e4] = av[bi];
            }
        }
        __syncthreads();

        if (tid < K1_BPB * NBO) {
            int bi = tid / NBO, n = tid % NBO;
            float s[NKEY];
            float mx = -1e30f;
            for (int j = 0; j < NKEY; j++) {
                float a = 0.f;
                for (int e = 0; e < DKQ; e++) a += sq[bi][n][e] * sk[bi][j][e];
                a *= 0.125f;
                s[j] = a;
                mx = fmaxf(mx, a);
            }
            float den = 0.f;
            for (int j = 0; j < NKEY; j++) { s[j] = expf(s[j] - mx); den += s[j]; }
            float inv = 1.0f / den;
            for (int j = 0; j < NKEY; j++) sattn[bi][n][j] = s[j] * inv;
        }
        __syncthreads();

        if (tid < K1_BPB) {
            int bi = tid;
            float sc[NBO], t[NBO];
            for (int n = 0; n < NBO; n++) { sc[n] = sattn[bi][n][0]; t[n] = sc[n]; }
            for (int a = 0; a < 4; a++) {
                int mi = a;
                for (int b = a + 1; b < NBO; b++) if (t[b] > t[mi]) mi = b;
                float tmp = t[a]; t[a] = t[mi]; t[mi] = tmp;
            }
            float thr = t[3] - 0.01f;
            for (int n = 0; n < NBO; n++) {
                float m = (sc[n] > thr) ? 1.0f : 0.0f;
                smb[bi][n] = m;
                g_mblk[(size_t)(b0 + bi) * NBO + n] = m;
            }
        }
        __syncthreads();

        for (int i = tid; i < K1_BPB * NBO * DKQ; i += 256) {
            int bi = i / (NBO * DKQ);
            int r  = i % (NBO * DKQ);
            int n  = r / DKQ;
            int e  = r % DKQ;
            float a = 0.f;
            for (int j = 0; j < NKEY; j++) a += sattn[bi][n][j] * sv[bi][j][e];
            so[bi][n][e] = a;
        }
        __syncthreads();

        for (int round = 0; round < 4; round++) {
            int g  = round * 256 + tid;
            int n  = g >> 7;
            int c4 = (g & 127) * 4;
            float4 bias = *(const float4*)&fcb[c4];
            float4 a[K1_BPB];
#pragma unroll
            for (int bi = 0; bi < K1_BPB; bi++) a[bi] = bias;
#pragma unroll 4
            for (int e = 0; e < DKQ; e++) {
                float4 w4 = *(const float4*)&fcw[(size_t)e * BSO + c4];
#pragma unroll
                for (int bi = 0; bi < K1_BPB; bi++) {
                    float s = so[bi][n][e];
                    a[bi].x += s * w4.x; a[bi].y += s * w4.y;
                    a[bi].z += s * w4.z; a[bi].w += s * w4.w;
                }
            }
#pragma unroll
            for (int bi = 0; bi < K1_BPB; bi++) {
                float xs[4] = {a[bi].x, a[bi].y, a[bi].z, a[bi].w};
                union { __nv_bfloat16 h[4]; uint2 u; } vh, vl;
#pragma unroll
                for (int j = 0; j < 4; j++) {
                    __nv_bfloat16 hi = __float2bfloat16(xs[j]);
                    vh.h[j] = hi;
                    vl.h[j] = __float2bfloat16(xs[j] - __bfloat162float(hi));
                }
                size_t ao = ((size_t)n * 1024 + (b0 + bi)) * 1024 + c4;
                *(uint2*)&g_ahi[ao] = vh.u;
                *(uint2*)&g_alo[ao] = vl.u;
                float m = smb[bi][n];
                *(float4*)&mask_out[(size_t)(b0 + bi) * NHID + n * BSO + c4] = make_float4(m, m, m, m);
            }
        }
    } else if (bid < K1_BLOCKS + PB_BLOCKS) {
        auto& ts = su.ts;
        const int pb = bid - K1_BLOCKS;
        const int n0 = (pb & 31) * 64;
        const int k0 = ((pb >> 5) & 15) * 64;
        const int kb = pb >> 9;

        const float* srcm = (k0 < 512) ? (w_ih + (size_t)kb * 512 * GATES)
                                       : (w_hh + (size_t)kb * 512 * GATES);
        const int krow0 = (k0 < 512) ? k0 : (k0 - 512);

#pragma unroll
        for (int p = 0; p < 16; p++) {
            int idx = p * 256 + tid;
            int r = idx >> 6;
            int c = idx & 63;
            ts[r][c] = srcm[(size_t)(krow0 + r) * GATES + n0 + c];
        }
        __syncthreads();

#pragma unroll
        for (int g = 0; g < 2; g++) {
            int n   = (tid >> 3) + g * 32;
            int kk0 = (tid & 7) * 8;
            union { __nv_bfloat16 h[8]; uint4 u; } vh, vl;
#pragma unroll
            for (int j = 0; j < 8; j++) {
                float x = ts[kk0 + j][n];
                __nv_bfloat16 hi = __float2bfloat16(x);
                vh.h[j] = hi;
                vl.h[j] = __float2bfloat16(x - __bfloat162float(hi));
            }
            size_t o = ((size_t)kb * GATES + n0 + n) * 1024 + k0 + kk0;
            *(uint4*)&g_bhi[o] = vh.u;
            *(uint4*)&g_blo[o] = vl.u;
        }
    } else if (bid < K1_BLOCKS + PB_BLOCKS + PA_BLOCKS) {
        size_t idx = (size_t)(bid - K1_BLOCKS - PB_BLOCKS) * 256 + tid;
        int k8 = (int)(idx & 63);
        int m  = (int)((idx >> 6) & 1023);
        int kb = (int)(idx >> 16);
        int k  = k8 * 8;

        const float* src = &hx[(size_t)m * NHID + kb * BSO + k];
        float4 a = *(const float4*)src;
        float4 b = *(const float4*)(src + 4);
        float xs[8] = {a.x, a.y, a.z, a.w, b.x, b.y, b.z, b.w};
        union { __nv_bfloat16 h[8]; uint4 u; } vh, vl;
#pragma unroll
        for (int j = 0; j < 8; j++) {
            __nv_bfloat16 hi = __float2bfloat16(xs[j]);
            vh.h[j] = hi;
            vl.h[j] = __float2bfloat16(xs[j] - __bfloat162float(hi));
        }
        size_t o = ((size_t)kb * 1024 + m) * 1024 + 512 + k;
        *(uint4*)&g_ahi[o] = vh.u;
        *(uint4*)&g_alo[o] = vl.u;
    } else {
        // ---- prep_wqkv: transpose + hi/lo split of mha wq/wk/wv ----
        auto& ts = su.ts;
        const int pw  = bid - K1_BLOCKS - PB_BLOCKS - PA_BLOCKS;
        const int mat = pw >> 6;
        const int kb  = (pw >> 3) & 7;
        const int kt  = pw & 7;
        const float* wsrc = ((mat == 0) ? mwq : (mat == 1) ? mwk : mwv)
                            + (size_t)kb * BSO * DKQ;

#pragma unroll
        for (int p = 0; p < 16; p++) {
            int idx = p * 256 + tid;
            int r = idx >> 6;
            int c = idx & 63;
            ts[r][c] = wsrc[(size_t)(kt * 64 + r) * DKQ + c];
        }
        __syncthreads();

#pragma unroll
        for (int g = 0; g < 2; g++) {
            int n   = (tid >> 3) + g * 32;
            int kk0 = (tid & 7) * 8;
            union { __nv_bfloat16 h[8]; uint4 u; } vh, vl;
#pragma unroll
            for (int j = 0; j < 8; j++) {
                float x = ts[kk0 + j][n];
                __nv_bfloat16 hi = __float2bfloat16(x);
                vh.h[j] = hi;
                vl.h[j] = __float2bfloat16(x - __bfloat162float(hi));
            }
            size_t o = ((size_t)(mat * 8 + kb) * 64 + n) * 512 + kt * 64 + kk0;
            *(uint4*)&g_wqhi[o] = vh.u;
            *(uint4*)&g_wqlo[o] = vl.u;
        }
    }
}

// =====================================================================
// K2M: LSTM gate GEMM (mma.sync bf16, hi/lo 3 passes), proven config.
// =====================================================================
#define K2_STG   32768
#define K2_SMEM  (3 * K2_STG)
#define OFF_AH   0
#define OFF_AL   8192
#define OFF_BH   16384
#define OFF_BL   24576

__global__ void __launch_bounds__(256, 2) k2m_gemm()
{
    extern __shared__ char smem[];
    const int tid = threadIdx.x;
    const int wid = tid >> 5;
    const int lid = tid & 31;
    const uint32_t sbase = smem_u32(smem);
    const int nb = blockIdx.x * 128;
    const int mb = blockIdx.y * 128;
    const int kb = blockIdx.z;

    const __nv_bfloat16* Ah = g_ahi + ((size_t)kb * 1024 + mb) * 1024;
    const __nv_bfloat16* Al = g_alo + ((size_t)kb * 1024 + mb) * 1024;
    const __nv_bfloat16* Bh = g_bhi + ((size_t)kb * 2048 + nb) * 1024;
    const __nv_bfloat16* Bl = g_blo + ((size_t)kb * 2048 + nb) * 1024;

    const int mw = (wid >> 2) * 64;
    const int nw = (wid & 3) * 32;
    const int g  = lid >> 3;
    const int r  = lid & 7;

    uint32_t offA[4][2], offB[2][2];
#pragma unroll
    for (int i = 0; i < 4; i++)
#pragma unroll
        for (int ks = 0; ks < 2; ks++) {
            int m = mw + i * 16 + (g & 1) * 8 + r;
            int k = ks * 16 + (g >> 1) * 8;
            offA[i][ks] = swz64((uint32_t)(m * 64 + k * 2));
        }
#pragma unroll
    for (int j = 0; j < 2; j++)
#pragma unroll
        for (int ks = 0; ks < 2; ks++) {
            int n = nw + j * 16 + (g & 1) * 8 + r;
            int k = ks * 16 + (g >> 1) * 8;
            offB[j][ks] = swz64((uint32_t)(n * 64 + k * 2));
        }

    float acc[4][4][4];
#pragma unroll
    for (int i = 0; i < 4; i++)
#pragma unroll
        for (int j = 0; j < 4; j++)
#pragma unroll
            for (int c = 0; c < 4; c++) acc[i][j][c] = 0.f;

    const int c_row0 = tid >> 2;
    const int c_sl   = tid & 3;
    const uint32_t c_d0 = swz64((uint32_t)(c_row0 * 64 + c_sl * 16));
    const uint32_t c_d1 = swz64((uint32_t)((c_row0 + 64) * 64 + c_sl * 16));
    const size_t  c_g0 = (size_t)c_row0 * 1024 + c_sl * 8;
    const size_t  c_g1 = (size_t)(c_row0 + 64) * 1024 + c_sl * 8;

#pragma unroll
    for (int pc = 0; pc < 2; pc++) {
        uint32_t sb = sbase + pc * K2_STG;
        int kc = pc * 32;
        cpa16(sb + OFF_AH + c_d0, Ah + c_g0 + kc);
        cpa16(sb + OFF_AL + c_d0, Al + c_g0 + kc);
        cpa16(sb + OFF_BH + c_d0, Bh + c_g0 + kc);
        cpa16(sb + OFF_BL + c_d0, Bl + c_g0 + kc);
        cpa16(sb + OFF_AH + c_d1, Ah + c_g1 + kc);
        cpa16(sb + OFF_AL + c_d1, Al + c_g1 + kc);
        cpa16(sb + OFF_BH + c_d1, Bh + c_g1 + kc);
        cpa16(sb + OFF_BL + c_d1, Bl + c_g1 + kc);
        cp_commit();
    }

    int stage = 0;
    int pstage = 2;
    for (int ch = 0; ch < 32; ch++) {
        if (ch + 1 < 32) cp_wait1(); else cp_wait0();
        __syncthreads();

        if (ch + 2 < 32) {
            uint32_t sb = sbase + pstage * K2_STG;
            int kc = (ch + 2) * 32;
            cpa16(sb + OFF_AH + c_d0, Ah + c_g0 + kc);
            cpa16(sb + OFF_AL + c_d0, Al + c_g0 + kc);
            cpa16(sb + OFF_BH + c_d0, Bh + c_g0 + kc);
            cpa16(sb + OFF_BL + c_d0, Bl + c_g0 + kc);
            cpa16(sb + OFF_AH + c_d1, Ah + c_g1 + kc);
            cpa16(sb + OFF_AL + c_d1, Al + c_g1 + kc);
            cpa16(sb + OFF_BH + c_d1, Bh + c_g1 + kc);
            cpa16(sb + OFF_BL + c_d1, Bl + c_g1 + kc);
            cp_commit();
        }

        uint32_t sb = sbase + stage * K2_STG;
#pragma unroll
        for (int ks = 0; ks < 2; ks++) {
            uint32_t bh[2][4], bl[2][4];
#pragma unroll
            for (int j = 0; j < 2; j++) {
                ldsm_x4(sb + OFF_BH + offB[j][ks], bh[j]);
                ldsm_x4(sb + OFF_BL + offB[j][ks], bl[j]);
            }
#pragma unroll
            for (int i = 0; i < 4; i++) {
                uint32_t ah[4], al[4];
                ldsm_x4(sb + OFF_AH + offA[i][ks], ah);
                ldsm_x4(sb + OFF_AL + offA[i][ks], al);
#pragma unroll
                for (int jn = 0; jn < 4; jn++) {
                    const int jj = jn >> 1;
                    const int ss = jn & 1;
                    mma_bf16(acc[i][jn], ah, bh[jj][ss], bh[jj][ss + 2]);
                    mma_bf16(acc[i][jn], ah, bl[jj][ss], bl[jj][ss + 2]);
                    mma_bf16(acc[i][jn], al, bh[jj][ss], bh[jj][ss + 2]);
                }
            }
        }
        stage  = (stage == 2) ? 0 : stage + 1;
        pstage = (pstage == 2) ? 0 : pstage + 1;
    }

    const int rowc = lid >> 2;
    const int colc = (lid & 3) * 2;
#pragma unroll
    for (int i = 0; i < 4; i++) {
        int m0 = mb + mw + i * 16 + rowc;
#pragma unroll
        for (int jn = 0; jn < 4; jn++) {
            int n0 = nb + nw + jn * 8 + colc;
            *(float2*)&g_gates[((size_t)m0 * NBO + kb) * GATES + n0] =
                make_float2(acc[i][jn][0], acc[i][jn][1]);
            *(float2*)&g_gates[((size_t)(m0 + 8) * NBO + kb) * GATES + n0] =
                make_float2(acc[i][jn][2], acc[i][jn][3]);
        }
    }
}

// =====================================================================
// K3: LSTM elementwise, float4-vectorized; also emits h_new bf16 hi/lo.
// =====================================================================
__global__ void __launch_bounds__(256) k3_lstm_ew(
    const float* __restrict__ cx, const float* __restrict__ b_ih,
    const float* __restrict__ b_hh, float* __restrict__ cx_out)
{
    size_t i4 = (size_t)blockIdx.x * blockDim.x + threadIdx.x;
    size_t bk = i4 >> 7;
    int kb = (int)(bk & 7);
    int d  = (int)(i4 & 127) * 4;
    const float* g  = &g_gates[bk * GATES];
    const float* bi = &b_ih[(size_t)kb * GATES];
    const float* bh = &b_hh[(size_t)kb * GATES];

    float4 gi = *(const float4*)&g[d];
    float4 gf = *(const float4*)&g[d + 512];
    float4 gg = *(const float4*)&g[d + 1024];
    float4 go = *(const float4*)&g[d + 1536];
    float4 bi_i = *(const float4*)&bi[d],        bh_i = *(const float4*)&bh[d];
    float4 bi_f = *(const float4*)&bi[d + 512],  bh_f = *(const float4*)&bh[d + 512];
    float4 bi_g = *(const float4*)&bi[d + 1024], bh_g = *(const float4*)&bh[d + 1024];
    float4 bi_o = *(const float4*)&bi[d + 1536], bh_o = *(const float4*)&bh[d + 1536];
    float4 cb = *(const float4*)&cx[bk * BSO + d];
    float m = g_mblk[bk];

    float hn[4], co[4];
    float giv[4] = {gi.x, gi.y, gi.z, gi.w};
    float gfv[4] = {gf.x, gf.y, gf.z, gf.w};
    float ggv[4] = {gg.x, gg.y, gg.z, gg.w};
    float gov[4] = {go.x, go.y, go.z, go.w};
    float biiv[4] = {bi_i.x, bi_i.y, bi_i.z, bi_i.w};
    float bhiv[4] = {bh_i.x, bh_i.y, bh_i.z, bh_i.w};
    float bifv[4] = {bi_f.x, bi_f.y, bi_f.z, bi_f.w};
    float bhfv[4] = {bh_f.x, bh_f.y, bh_f.z, bh_f.w};
    float bigv[4] = {bi_g.x, bi_g.y, bi_g.z, bi_g.w};
    float bhgv[4] = {bh_g.x, bh_g.y, bh_g.z, bh_g.w};
    float biov[4] = {bi_o.x, bi_o.y, bi_o.z, bi_o.w};
    float bhov[4] = {bh_o.x, bh_o.y, bh_o.z, bh_o.w};
    float cbv[4] = {cb.x, cb.y, cb.z, cb.w};
#pragma unroll
    for (int j = 0; j < 4; j++) {
        float ig = sigf(giv[j] + biiv[j] + bhiv[j]);
        float fg = sigf(gfv[j] + bifv[j] + bhfv[j]);
        float gt = tanhf(ggv[j] + bigv[j] + bhgv[j]);
        float og = sigf(gov[j] + biov[j] + bhov[j]);
        float cn = fg * cbv[j] + ig * gt;
        hn[j] = og * tanhf(cn);
        co[j] = m * cn + (1.0f - m) * cbv[j];
    }
    *(float4*)&g_hnew[bk * BSO + d]  = make_float4(hn[0], hn[1], hn[2], hn[3]);
    *(float4*)&cx_out[bk * BSO + d] = make_float4(co[0], co[1], co[2], co[3]);

    union { __nv_bfloat16 h[4]; uint2 u; } vh, vl;
#pragma unroll
    for (int j = 0; j < 4; j++) {
        __nv_bfloat16 hi = __float2bfloat16(hn[j]);
        vh.h[j] = hi;
        vl.h[j] = __float2bfloat16(hn[j] - __bfloat162float(hi));
    }
    size_t ho = ((size_t)kb * 1024 + (bk >> 3)) * 512 + d;
    *(uint2*)&g_h2hi[ho] = vh.u;
    *(uint2*)&g_h2lo[ho] = vl.u;
}

// =====================================================================
// K4M: q2/k2/v2 GEMMs on mma.sync bf16 (hi/lo 3 passes).  Proven R13.
// =====================================================================
#define K4_STG   24576
#define K4_SMEM  (2 * K4_STG)
#define K4_AH    0
#define K4_AL    8192
#define K4_BH    16384
#define K4_BL    20480

__global__ void __launch_bounds__(256) k4m_qkv()
{
    extern __shared__ char smem[];
    const int tid = threadIdx.x;
    const int wid = tid >> 5;
    const int lid = tid & 31;
    const uint32_t sbase = smem_u32(smem);
    const int mat = blockIdx.x;
    const int mb  = blockIdx.y * 128;
    const int kb  = blockIdx.z;

    const __nv_bfloat16* Ah = g_h2hi + ((size_t)kb * 1024 + mb) * 512;
    const __nv_bfloat16* Al = g_h2lo + ((size_t)kb * 1024 + mb) * 512;
    const __nv_bfloat16* Bh = g_wqhi + (size_t)(mat * 8 + kb) * 64 * 512;
    const __nv_bfloat16* Bl = g_wqlo + (size_t)(mat * 8 + kb) * 64 * 512;

    const int mw = (wid >> 1) * 32;
    const int nw = (wid & 1) * 32;
    const int g  = lid >> 3;
    const int r  = lid & 7;

    uint32_t offA[2][2], offB[2][2];
#pragma unroll
    for (int i = 0; i < 2; i++)
#pragma unroll
        for (int ks = 0; ks < 2; ks++) {
            int m = mw + i * 16 + (g & 1) * 8 + r;
            int k = ks * 16 + (g >> 1) * 8;
            offA[i][ks] = swz64((uint32_t)(m * 64 + k * 2));
        }
#pragma unroll
    for (int j = 0; j < 2; j++)
#pragma unroll
        for (int ks = 0; ks < 2; ks++) {
            int n = nw + j * 16 + (g & 1) * 8 + r;
            int k = ks * 16 + (g >> 1) * 8;
            offB[j][ks] = swz64((uint32_t)(n * 64 + k * 2));
        }

    float acc[2][4][4];
#pragma unroll
    for (int i = 0; i < 2; i++)
#pragma unroll
        for (int j = 0; j < 4; j++)
#pragma unroll
            for (int c = 0; c < 4; c++) acc[i][j][c] = 0.f;

    const int a_row = tid >> 2;
    const int a_sl  = tid & 3;
    const uint32_t a_d0 = swz64((uint32_t)(a_row * 64 + a_sl * 16));
    const uint32_t a_d1 = swz64((uint32_t)((a_row + 64) * 64 + a_sl * 16));
    const size_t  a_g0 = (size_t)a_row * 512 + a_sl * 8;
    const size_t  a_g1 = (size_t)(a_row + 64) * 512 + a_sl * 8;
    const uint32_t b_d  = swz64((uint32_t)(a_row * 64 + a_sl * 16));
    const size_t  b_g  = (size_t)a_row * 512 + a_sl * 8;
    const bool b_act = (a_row < 64);

    {
        uint32_t sb = sbase;
        cpa16(sb + K4_AH + a_d0, Ah + a_g0);
        cpa16(sb + K4_AL + a_d0, Al + a_g0);
        cpa16(sb + K4_AH + a_d1, Ah + a_g1);
        cpa16(sb + K4_AL + a_d1, Al + a_g1);
        if (b_act) {
            cpa16(sb + K4_BH + b_d, Bh + b_g);
            cpa16(sb + K4_BL + b_d, Bl + b_g);
        }
        cp_commit();
    }

    for (int ch = 0; ch < 16; ch++) {
        if (ch + 1 < 16) {
            uint32_t sb = sbase + ((ch + 1) & 1) * K4_STG;
            int kc = (ch + 1) * 32;
            cpa16(sb + K4_AH + a_d0, Ah + a_g0 + kc);
            cpa16(sb + K4_AL + a_d0, Al + a_g0 + kc);
            cpa16(sb + K4_AH + a_d1, Ah + a_g1 + kc);
            cpa16(sb + K4_AL + a_d1, Al + a_g1 + kc);
            if (b_act) {
                cpa16(sb + K4_BH + b_d, Bh + b_g + kc);
                cpa16(sb + K4_BL + b_d, Bl + b_g + kc);
            }
            cp_commit();
            cp_wait1();
        } else {
            cp_wait0();
        }
        __syncthreads();

        uint32_t sb = sbase + (ch & 1) * K4_STG;
#pragma unroll
        for (int ks = 0; ks < 2; ks++) {
            uint32_t bh[2][4], bl[2][4];
#pragma unroll
            for (int j = 0; j < 2; j++) {
                ldsm_x4(sb + K4_BH + offB[j][ks], bh[j]);
                ldsm_x4(sb + K4_BL + offB[j][ks], bl[j]);
            }
#pragma unroll
            for (int i = 0; i < 2; i++) {
                uint32_t ah[4], al[4];
                ldsm_x4(sb + K4_AH + offA[i][ks], ah);
                ldsm_x4(sb + K4_AL + offA[i][ks], al);
#pragma unroll
                for (int jn = 0; jn < 4; jn++) {
                    const int jj = jn >> 1;
                    const int ss = jn & 1;
                    mma_bf16(acc[i][jn], ah, bh[jj][ss], bh[jj][ss + 2]);
                    mma_bf16(acc[i][jn], ah, bl[jj][ss], bl[jj][ss + 2]);
                    mma_bf16(acc[i][jn], al, bh[jj][ss], bh[jj][ss + 2]);
                }
            }
        }
        __syncthreads();
    }

    float* dst = (mat == 0) ? g_q2 : (mat == 1) ? g_k2 : g_v2;
    const int rowc = lid >> 2;
    const int colc = (lid & 3) * 2;
#pragma unroll
    for (int i = 0; i < 2; i++) {
        int m0 = mb + mw + i * 16 + rowc;
#pragma unroll
        for (int jn = 0; jn < 4; jn++) {
            int n0 = nw + jn * 8 + colc;
            *(float2*)&dst[((size_t)m0 * NBO + kb) * DKQ + n0] =
                make_float2(acc[i][jn][0], acc[i][jn][1]);
            *(float2*)&dst[((size_t)(m0 + 8) * NBO + kb) * DKQ + n0] =
                make_float2(acc[i][jn][2], acc[i][jn][3]);
        }
    }
}

// =====================================================================
// K5: MHA attend + fc/gate + final hx_out combine.  FFMA2 accumulators.
// =====================================================================
__global__ void __launch_bounds__(256) k5_mha(
    const float* __restrict__ hx,
    const float* __restrict__ fcw, const float* __restrict__ fcb,
    const float* __restrict__ gw,  const float* __restrict__ gb,
    float* __restrict__ hx_out)
{
    __shared__ float sq2[NBO][DKQ];
    __shared__ float sk2[NBO][DKQ];
    __shared__ float sv2[NBO][DKQ];
    __shared__ float sat[NBO][NBO];
    __shared__ float so2[NBO][DKQ];

    const int tid = threadIdx.x;
    const size_t b = blockIdx.x;

    for (int i = tid; i < NBO * DKQ; i += 256) {
        ((float*)sq2)[i] = g_q2[b * NBO * DKQ + i];
        ((float*)sk2)[i] = g_k2[b * NBO * DKQ + i];
        ((float*)sv2)[i] = g_v2[b * NBO * DKQ + i];
    }
    __syncthreads();

    if (tid < 64) {
        int kq = tid >> 3, kj = tid & 7;
        float s = 0.f;
        for (int e = 0; e < DKQ; e++) s += sq2[kq][e] * sk2[kj][e];
        sat[kq][kj] = s * 0.125f;
    }
    __syncthreads();
    if (tid < NBO) {
        float mx = -1e30f;
        for (int j = 0; j < NBO; j++) mx = fmaxf(mx, sat[tid][j]);
        float den = 0.f;
        for (int j = 0; j < NBO; j++) { float e = expf(sat[tid][j] - mx); sat[tid][j] = e; den += e; }
        float inv = 1.0f / den;
        for (int j = 0; j < NBO; j++) sat[tid][j] *= inv;
    }
    __syncthreads();
    for (int i = tid; i < NBO * DKQ; i += 256) {
        int k = i >> 6, e = i & 63;
        float a = 0.f;
        for (int j = 0; j < NBO; j++) a += sat[k][j] * sv2[j][e];
        so2[k][e] = a;
    }
    __syncthreads();

    const int d0 = tid * 2;
    unsigned long long aof[NBO], agf[NBO];
#pragma unroll
    for (int k = 0; k < NBO; k++) { aof[k] = 0ULL; agf[k] = 0ULL; }

    for (int e = 0; e < DKQ; e++) {
        float2 fw  = *(const float2*)&fcw[(size_t)e * BSO + d0];
        float2 gwv = *(const float2*)&gw[(size_t)e * BSO + d0];
        unsigned long long fwp = pk2(fw.x, fw.y);
        unsigned long long gwp = pk2(gwv.x, gwv.y);
#pragma unroll
        for (int k = 0; k < NBO; k++) {
            float o = so2[k][e];
            unsigned long long oo = pk2(o, o);
            fma2(aof[k], oo, fwp);
            fma2(agf[k], oo, gwp);
        }
    }

    float fb0 = fcb[d0], fb1 = fcb[d0 + 1];
    float gb0 = gb[d0],  gb1 = gb[d0 + 1];
#pragma unroll
    for (int k = 0; k < NBO; k++) {
        float2 ao = upk2(aof[k]);
        float2 ag = upk2(agf[k]);
        float m = g_mblk[b * NBO + k];
        float hn0 = g_hnew[(b * NBO + k) * BSO + d0];
        float hn1 = g_hnew[(b * NBO + k) * BSO + d0 + 1];
        float v0 = hn0 + sigf(ag.x + gb0) * tanhf(ao.x + fb0);
        float v1 = hn1 + sigf(ag.y + gb1) * tanhf(ao.y + fb1);
        size_t idx = b * NHID + (size_t)k * BSO + d0;
        hx_out[idx]     = m * v0 + (1.0f - m) * hx[idx];
        hx_out[idx + 1] = m * v1 + (1.0f - m) * hx[idx + 1];
    }
}

// =====================================================================
extern "C" void kernel_launch(void* const* d_in, const int* in_sizes, int n_in,
                              void* d_out, int out_size) {
    const float* inp    = (const float*)d_in[0];
    const float* hx     = (const float*)d_in[1];
    const float* cx     = (const float*)d_in[2];
    const float* ia_wq  = (const float*)d_in[3];
    const float* ia_wk  = (const float*)d_in[4];
    const float* ia_wv  = (const float*)d_in[5];
    const float* ia_fcw = (const float*)d_in[6];
    const float* ia_fcb = (const float*)d_in[7];
    const float* mha_wq = (const float*)d_in[8];
    const float* mha_wk = (const float*)d_in[9];
    const float* mha_wv = (const float*)d_in[10];
    const float* mha_fcw= (const float*)d_in[11];
    const float* mha_fcb= (const float*)d_in[12];
    const float* mha_gw = (const float*)d_in[13];
    const float* mha_gb = (const float*)d_in[14];
    const float* w_ih   = (const float*)d_in[15];
    const float* w_hh   = (const float*)d_in[16];
    const float* b_ih   = (const float*)d_in[17];
    const float* b_hh   = (const float*)d_in[18];

    float* out   = (float*)d_out;
    const size_t N = (size_t)BSZ * NHID;
    float* out_hx   = out;
    float* out_cx   = out + N;
    float* out_mask = out + 2 * N;

    cudaFuncSetAttribute(k2m_gemm, cudaFuncAttributeMaxDynamicSharedMemorySize, K2_SMEM);
    cudaFuncSetAttribute(k4m_qkv, cudaFuncAttributeMaxDynamicSharedMemorySize, K4_SMEM);

    k_pre<<<PRE_BLOCKS, 256>>>(inp, hx, ia_wq, ia_wk, ia_wv, ia_fcw, ia_fcb,
                               w_ih, w_hh, mha_wq, mha_wk, mha_wv, out_mask);
    k2m_gemm<<<dim3(GATES / 128, BSZ / 128, NBO), 256, K2_SMEM>>>();
    k3_lstm_ew<<<(unsigned)(((size_t)BSZ * NBO * BSO / 4 + 255) / 256), 256>>>(cx, b_ih, b_hh, out_cx);
    k4m_qkv<<<dim3(3, BSZ / 128, NBO), 256, K4_SMEM>>>();
    k5_mha<<<BSZ, 256>>>(hx, mha_fcw, mha_fcb, mha_gw, mha_gb, out_hx);
}

// round 15
// speedup vs baseline: 1.1004x; 1.0090x over previous
#include <cuda_runtime.h>
#include <cuda_bf16.h>
#include <math.h>
#include <stdint.h>

#define BSZ   1024
#define NBIN  4
#define BSIN  128
#define NKEY  5
#define NBO   8
#define BSO   512
#define NHID  4096
#define DKQ   64
#define GATES 2048

// ------------- scratch (allocation-free: __device__ globals) -------------
__device__ float g_gates  [(size_t)BSZ * NBO * GATES];
__device__ float g_hnew   [(size_t)BSZ * NBO * BSO];
__device__ float g_q2     [(size_t)BSZ * NBO * DKQ];
__device__ float g_k2     [(size_t)BSZ * NBO * DKQ];
__device__ float g_v2     [(size_t)BSZ * NBO * DKQ];
__device__ float g_mblk   [(size_t)BSZ * NBO];
// bf16 hi/lo split operands for the tensor-core LSTM GEMM
__device__ __nv_bfloat16 g_ahi[(size_t)NBO * 1024 * 1024];
__device__ __nv_bfloat16 g_alo[(size_t)NBO * 1024 * 1024];
__device__ __nv_bfloat16 g_bhi[(size_t)NBO * 2048 * 1024];
__device__ __nv_bfloat16 g_blo[(size_t)NBO * 2048 * 1024];
// bf16 hi/lo split of h_new: [kb][m=1024][k=512]
__device__ __nv_bfloat16 g_h2hi[(size_t)NBO * 1024 * 512];
__device__ __nv_bfloat16 g_h2lo[(size_t)NBO * 1024 * 512];
// bf16 hi/lo split of mha wq/wk/wv transposed: [mat*8+kb][n=64][k=512]
__device__ __nv_bfloat16 g_wqhi[(size_t)3 * NBO * 64 * 512];
__device__ __nv_bfloat16 g_wqlo[(size_t)3 * NBO * 64 * 512];

__device__ __forceinline__ float sigf(float x) { return 1.0f / (1.0f + expf(-x)); }

// ------------- f32x2 packed FMA helpers -------------
__device__ __forceinline__ unsigned long long pk2(float x, float y) {
    unsigned long long r;
    asm("mov.b64 %0, {%1, %2};" : "=l"(r) : "f"(x), "f"(y));
    return r;
}
__device__ __forceinline__ void fma2(unsigned long long& d, unsigned long long a, unsigned long long b) {
    asm("fma.rn.f32x2 %0, %1, %2, %0;" : "+l"(d) : "l"(a), "l"(b));
}
__device__ __forceinline__ float2 upk2(unsigned long long v) {
    float2 f;
    asm("mov.b64 {%0, %1}, %2;" : "=f"(f.x), "=f"(f.y) : "l"(v));
    return f;
}

// ------------- mma.sync / ldmatrix / cp.async helpers -------------
__device__ __forceinline__ uint32_t smem_u32(const void* p) {
    uint32_t a;
    asm("{ .reg .u64 t; cvta.to.shared.u64 t, %1; cvt.u32.u64 %0, t; }" : "=r"(a) : "l"(p));
    return a;
}
__device__ __forceinline__ uint32_t swz64(uint32_t b) { return b ^ ((b >> 3) & 0x30); }

__device__ __forceinline__ void ldsm_x4(uint32_t addr, uint32_t* r) {
    asm volatile("ldmatrix.sync.aligned.m8n8.x4.shared.b16 {%0,%1,%2,%3}, [%4];"
                 : "=r"(r[0]), "=r"(r[1]), "=r"(r[2]), "=r"(r[3]) : "r"(addr));
}
__device__ __forceinline__ void mma_bf16(float* c, const uint32_t* a, uint32_t b0, uint32_t b1) {
    asm volatile("mma.sync.aligned.m16n8k16.row.col.f32.bf16.bf16.f32 "
                 "{%0,%1,%2,%3}, {%4,%5,%6,%7}, {%8,%9}, {%0,%1,%2,%3};"
                 : "+f"(c[0]), "+f"(c[1]), "+f"(c[2]), "+f"(c[3])
                 : "r"(a[0]), "r"(a[1]), "r"(a[2]), "r"(a[3]), "r"(b0), "r"(b1));
}
__device__ __forceinline__ void cpa16(uint32_t dst, const void* src) {
    asm volatile("cp.async.cg.shared.global [%0], [%1], 16;" :: "r"(dst), "l"(src));
}
__device__ __forceinline__ void cp_commit() { asm volatile("cp.async.commit_group;"); }
__device__ __forceinline__ void cp_wait1() { asm volatile("cp.async.wait_group 1;"); }
__device__ __forceinline__ void cp_wait0() { asm volatile("cp.async.wait_group 0;"); }

// =====================================================================
// K_PRE: fused (k1 input-attention | prep_b | prep_a2 | prep_wqkv).
// =====================================================================
#define K1_BPB 4
#define K1_BLOCKS   (BSZ / K1_BPB)                /* 256  */
#define PB_BLOCKS   (32 * 16 * 8)                 /* 4096 */
#define PA_BLOCKS   2048
#define PW_BLOCKS   (3 * 8 * 8)                   /* 192  */
#define PRE_BLOCKS  (K1_BLOCKS + PB_BLOCKS + PA_BLOCKS + PW_BLOCKS)

struct K1Smem {
    float sx[K1_BPB][NKEY * BSIN];
    float sk[K1_BPB][NKEY][DKQ];
    float sv[K1_BPB][NKEY][DKQ];
    float sq[K1_BPB][NBO][DKQ];
    float so[K1_BPB][NBO][DKQ];
    float sattn[K1_BPB][NBO][NKEY];
    float smb[K1_BPB][NBO];
};
union PreSmem {
    K1Smem k1;
    float ts[64][65];
};

__global__ void __launch_bounds__(256) k_pre(
    const float* __restrict__ inp, const float* __restrict__ hx,
    const float* __restrict__ wq, const float* __restrict__ wk, const float* __restrict__ wv,
    const float* __restrict__ fcw, const float* __restrict__ fcb,
    const float* __restrict__ w_ih, const float* __restrict__ w_hh,
    const float* __restrict__ mwq, const float* __restrict__ mwk, const float* __restrict__ mwv,
    float* __restrict__ mask_out)
{
    __shared__ PreSmem su;
    const int tid = threadIdx.x;
    const int bid = blockIdx.x;

    if (bid < K1_BLOCKS) {
        auto& sx = su.k1.sx;  auto& sk = su.k1.sk;  auto& sv = su.k1.sv;
        auto& sq = su.k1.sq;  auto& so = su.k1.so;
        auto& sattn = su.k1.sattn;  auto& smb = su.k1.smb;
        const int b0 = bid * K1_BPB;

        for (int i = tid; i < K1_BPB * NKEY * BSIN; i += 256) {
            int bi = i / (NKEY * BSIN);
            int j  = i % (NKEY * BSIN);
            sx[bi][j] = (j < NBIN * BSIN) ? inp[(size_t)(b0 + bi) * (NBIN * BSIN) + j] : 0.0f;
        }
        __syncthreads();

        if (tid < 128) {
            const int n  = tid >> 4;
            const int e4 = (tid & 15) * 4;
            const float* wp = wq + (size_t)(n * BSO) * DKQ + e4;
            float4 aq[K1_BPB];
#pragma unroll
            for (int bi = 0; bi < K1_BPB; bi++) aq[bi] = make_float4(0.f, 0.f, 0.f, 0.f);
            for (int d = 0; d < BSO; d += 4) {
                float4 hv4[K1_BPB];
#pragma unroll
                for (int bi = 0; bi < K1_BPB; bi++)
                    hv4[bi] = *(const float4*)&hx[(size_t)(b0 + bi) * NHID + n * BSO + d];
#pragma unroll
                for (int dd = 0; dd < 4; dd++) {
                    float4 w4 = *(const float4*)(wp + (size_t)(d + dd) * DKQ);
#pragma unroll
                    for (int bi = 0; bi < K1_BPB; bi++) {
                        float hv = (dd == 0) ? hv4[bi].x : (dd == 1) ? hv4[bi].y
                                 : (dd == 2) ? hv4[bi].z : hv4[bi].w;
                        aq[bi].x += hv * w4.x; aq[bi].y += hv * w4.y;
                        aq[bi].z += hv * w4.z; aq[bi].w += hv * w4.w;
                    }
                }
            }
#pragma unroll
            for (int bi = 0; bi < K1_BPB; bi++) *(float4*)&sq[bi][n][e4] = aq[bi];
        } else if (tid < 128 + NKEY * 16) {
            const int g  = tid - 128;
            const int n  = g / 16;
            const int e4 = (g % 16) * 4;
            const float* wkp = wk + (size_t)(n * BSIN) * DKQ + e4;
            const float* wvp = wv + (size_t)(n * BSIN) * DKQ + e4;
            float4 ak[K1_BPB], av[K1_BPB];
#pragma unroll
            for (int bi = 0; bi < K1_BPB; bi++) {
                ak[bi] = make_float4(0.f, 0.f, 0.f, 0.f);
                av[bi] = make_float4(0.f, 0.f, 0.f, 0.f);
            }
#pragma unroll 4
            for (int d = 0; d < BSIN; d++) {
                float4 a4 = *(const float4*)(wkp + (size_t)d * DKQ);
                float4 b4 = *(const float4*)(wvp + (size_t)d * DKQ);
#pragma unroll
                for (int bi = 0; bi < K1_BPB; bi++) {
                    float xv = sx[bi][n * BSIN + d];
                    ak[bi].x += xv * a4.x; ak[bi].y += xv * a4.y;
                    ak[bi].z += xv * a4.z; ak[bi].w += xv * a4.w;
                    av[bi].x += xv * b4.x; av[bi].y += xv * b4.y;
                    av[bi].z += xv * b4.z; av[bi].w += xv * b4.w;
                }
            }
#pragma unroll
            for (int bi = 0; bi < K1_BPB; bi++) {
                *(float4*)&sk[bi][n][e4] = ak[bi];
                *(float4*)&sv[bi][n][e4] = av[bi];
            }
        }
        __syncthreads();

        if (tid < K1_BPB * NBO) {
            int bi = tid / NBO, n = tid % NBO;
            float s[NKEY];
            float mx = -1e30f;
            for (int j = 0; j < NKEY; j++) {
                float a = 0.f;
                for (int e = 0; e < DKQ; e++) a += sq[bi][n][e] * sk[bi][j][e];
                a *= 0.125f;
                s[j] = a;
                mx = fmaxf(mx, a);
            }
            float den = 0.f;
            for (int j = 0; j < NKEY; j++) { s[j] = expf(s[j] - mx); den += s[j]; }
            float inv = 1.0f / den;
            for (int j = 0; j < NKEY; j++) sattn[bi][n][j] = s[j] * inv;
        }
        __syncthreads();

        if (tid < K1_BPB) {
            int bi = tid;
            float sc[NBO], t[NBO];
            for (int n = 0; n < NBO; n++) { sc[n] = sattn[bi][n][0]; t[n] = sc[n]; }
            for (int a = 0; a < 4; a++) {
                int mi = a;
                for (int b = a + 1; b < NBO; b++) if (t[b] > t[mi]) mi = b;
                float tmp = t[a]; t[a] = t[mi]; t[mi] = tmp;
            }
            float thr = t[3] - 0.01f;
            for (int n = 0; n < NBO; n++) {
                float m = (sc[n] > thr) ? 1.0f : 0.0f;
                smb[bi][n] = m;
                g_mblk[(size_t)(b0 + bi) * NBO + n] = m;
            }
        }
        __syncthreads();

        for (int i = tid; i < K1_BPB * NBO * DKQ; i += 256) {
            int bi = i / (NBO * DKQ);
            int r  = i % (NBO * DKQ);
            int n  = r / DKQ;
            int e  = r % DKQ;
            float a = 0.f;
            for (int j = 0; j < NKEY; j++) a += sattn[bi][n][j] * sv[bi][j][e];
            so[bi][n][e] = a;
        }
        __syncthreads();

        for (int round = 0; round < 4; round++) {
            int g  = round * 256 + tid;
            int n  = g >> 7;
            int c4 = (g & 127) * 4;
            float4 bias = *(const float4*)&fcb[c4];
            float4 a[K1_BPB];
#pragma unroll
            for (int bi = 0; bi < K1_BPB; bi++) a[bi] = bias;
#pragma unroll 4
            for (int e = 0; e < DKQ; e++) {
                float4 w4 = *(const float4*)&fcw[(size_t)e * BSO + c4];
#pragma unroll
                for (int bi = 0; bi < K1_BPB; bi++) {
                    float s = so[bi][n][e];
                    a[bi].x += s * w4.x; a[bi].y += s * w4.y;
                    a[bi].z += s * w4.z; a[bi].w += s * w4.w;
                }
            }
#pragma unroll
            for (int bi = 0; bi < K1_BPB; bi++) {
                float xs[4] = {a[bi].x, a[bi].y, a[bi].z, a[bi].w};
                union { __nv_bfloat16 h[4]; uint2 u; } vh, vl;
#pragma unroll
                for (int j = 0; j < 4; j++) {
                    __nv_bfloat16 hi = __float2bfloat16(xs[j]);
                    vh.h[j] = hi;
                    vl.h[j] = __float2bfloat16(xs[j] - __bfloat162float(hi));
                }
                size_t ao = ((size_t)n * 1024 + (b0 + bi)) * 1024 + c4;
                *(uint2*)&g_ahi[ao] = vh.u;
                *(uint2*)&g_alo[ao] = vl.u;
                float m = smb[bi][n];
                *(float4*)&mask_out[(size_t)(b0 + bi) * NHID + n * BSO + c4] = make_float4(m, m, m, m);
            }
        }
    } else if (bid < K1_BLOCKS + PB_BLOCKS) {
        auto& ts = su.ts;
        const int pb = bid - K1_BLOCKS;
        const int n0 = (pb & 31) * 64;
        const int k0 = ((pb >> 5) & 15) * 64;
        const int kb = pb >> 9;

        const float* srcm = (k0 < 512) ? (w_ih + (size_t)kb * 512 * GATES)
                                       : (w_hh + (size_t)kb * 512 * GATES);
        const int krow0 = (k0 < 512) ? k0 : (k0 - 512);

#pragma unroll
        for (int p = 0; p < 16; p++) {
            int idx = p * 256 + tid;
            int r = idx >> 6;
            int c = idx & 63;
            ts[r][c] = srcm[(size_t)(krow0 + r) * GATES + n0 + c];
        }
        __syncthreads();

#pragma unroll
        for (int g = 0; g < 2; g++) {
            int n   = (tid >> 3) + g * 32;
            int kk0 = (tid & 7) * 8;
            union { __nv_bfloat16 h[8]; uint4 u; } vh, vl;
#pragma unroll
            for (int j = 0; j < 8; j++) {
                float x = ts[kk0 + j][n];
                __nv_bfloat16 hi = __float2bfloat16(x);
                vh.h[j] = hi;
                vl.h[j] = __float2bfloat16(x - __bfloat162float(hi));
            }
            size_t o = ((size_t)kb * GATES + n0 + n) * 1024 + k0 + kk0;
            *(uint4*)&g_bhi[o] = vh.u;
            *(uint4*)&g_blo[o] = vl.u;
        }
    } else if (bid < K1_BLOCKS + PB_BLOCKS + PA_BLOCKS) {
        size_t idx = (size_t)(bid - K1_BLOCKS - PB_BLOCKS) * 256 + tid;
        int k8 = (int)(idx & 63);
        int m  = (int)((idx >> 6) & 1023);
        int kb = (int)(idx >> 16);
        int k  = k8 * 8;

        const float* src = &hx[(size_t)m * NHID + kb * BSO + k];
        float4 a = *(const float4*)src;
        float4 b = *(const float4*)(src + 4);
        float xs[8] = {a.x, a.y, a.z, a.w, b.x, b.y, b.z, b.w};
        union { __nv_bfloat16 h[8]; uint4 u; } vh, vl;
#pragma unroll
        for (int j = 0; j < 8; j++) {
            __nv_bfloat16 hi = __float2bfloat16(xs[j]);
            vh.h[j] = hi;
            vl.h[j] = __float2bfloat16(xs[j] - __bfloat162float(hi));
        }
        size_t o = ((size_t)kb * 1024 + m) * 1024 + 512 + k;
        *(uint4*)&g_ahi[o] = vh.u;
        *(uint4*)&g_alo[o] = vl.u;
    } else {
        // ---- prep_wqkv: transpose + hi/lo split of mha wq/wk/wv ----
        auto& ts = su.ts;
        const int pw  = bid - K1_BLOCKS - PB_BLOCKS - PA_BLOCKS;
        const int mat = pw >> 6;
        const int kb  = (pw >> 3) & 7;
        const int kt  = pw & 7;
        const float* wsrc = ((mat == 0) ? mwq : (mat == 1) ? mwk : mwv)
                            + (size_t)kb * BSO * DKQ;

#pragma unroll
        for (int p = 0; p < 16; p++) {
            int idx = p * 256 + tid;
            int r = idx >> 6;
            int c = idx & 63;
            ts[r][c] = wsrc[(size_t)(kt * 64 + r) * DKQ + c];
        }
        __syncthreads();

#pragma unroll
        for (int g = 0; g < 2; g++) {
            int n   = (tid >> 3) + g * 32;
            int kk0 = (tid & 7) * 8;
            union { __nv_bfloat16 h[8]; uint4 u; } vh, vl;
#pragma unroll
            for (int j = 0; j < 8; j++) {
                float x = ts[kk0 + j][n];
                __nv_bfloat16 hi = __float2bfloat16(x);
                vh.h[j] = hi;
                vl.h[j] = __float2bfloat16(x - __bfloat162float(hi));
            }
            size_t o = ((size_t)(mat * 8 + kb) * 64 + n) * 512 + kt * 64 + kk0;
            *(uint4*)&g_wqhi[o] = vh.u;
            *(uint4*)&g_wqlo[o] = vl.u;
        }
    }
}

// =====================================================================
// K2M: LSTM gate GEMM (mma.sync bf16, hi/lo 3 passes), proven config.
// =====================================================================
#define K2_STG   32768
#define K2_SMEM  (3 * K2_STG)
#define OFF_AH   0
#define OFF_AL   8192
#define OFF_BH   16384
#define OFF_BL   24576

__global__ void __launch_bounds__(256, 2) k2m_gemm()
{
    extern __shared__ char smem[];
    const int tid = threadIdx.x;
    const int wid = tid >> 5;
    const int lid = tid & 31;
    const uint32_t sbase = smem_u32(smem);
    const int nb = blockIdx.x * 128;
    const int mb = blockIdx.y * 128;
    const int kb = blockIdx.z;

    const __nv_bfloat16* Ah = g_ahi + ((size_t)kb * 1024 + mb) * 1024;
    const __nv_bfloat16* Al = g_alo + ((size_t)kb * 1024 + mb) * 1024;
    const __nv_bfloat16* Bh = g_bhi + ((size_t)kb * 2048 + nb) * 1024;
    const __nv_bfloat16* Bl = g_blo + ((size_t)kb * 2048 + nb) * 1024;

    const int mw = (wid >> 2) * 64;
    const int nw = (wid & 3) * 32;
    const int g  = lid >> 3;
    const int r  = lid & 7;

    uint32_t offA[4][2], offB[2][2];
#pragma unroll
    for (int i = 0; i < 4; i++)
#pragma unroll
        for (int ks = 0; ks < 2; ks++) {
            int m = mw + i * 16 + (g & 1) * 8 + r;
            int k = ks * 16 + (g >> 1) * 8;
            offA[i][ks] = swz64((uint32_t)(m * 64 + k * 2));
        }
#pragma unroll
    for (int j = 0; j < 2; j++)
#pragma unroll
        for (int ks = 0; ks < 2; ks++) {
            int n = nw + j * 16 + (g & 1) * 8 + r;
            int k = ks * 16 + (g >> 1) * 8;
            offB[j][ks] = swz64((uint32_t)(n * 64 + k * 2));
        }

    float acc[4][4][4];
#pragma unroll
    for (int i = 0; i < 4; i++)
#pragma unroll
        for (int j = 0; j < 4; j++)
#pragma unroll
            for (int c = 0; c < 4; c++) acc[i][j][c] = 0.f;

    const int c_row0 = tid >> 2;
    const int c_sl   = tid & 3;
    const uint32_t c_d0 = swz64((uint32_t)(c_row0 * 64 + c_sl * 16));
    const uint32_t c_d1 = swz64((uint32_t)((c_row0 + 64) * 64 + c_sl * 16));
    const size_t  c_g0 = (size_t)c_row0 * 1024 + c_sl * 8;
    const size_t  c_g1 = (size_t)(c_row0 + 64) * 1024 + c_sl * 8;

#pragma unroll
    for (int pc = 0; pc < 2; pc++) {
        uint32_t sb = sbase + pc * K2_STG;
        int kc = pc * 32;
        cpa16(sb + OFF_AH + c_d0, Ah + c_g0 + kc);
        cpa16(sb + OFF_AL + c_d0, Al + c_g0 + kc);
        cpa16(sb + OFF_BH + c_d0, Bh + c_g0 + kc);
        cpa16(sb + OFF_BL + c_d0, Bl + c_g0 + kc);
        cpa16(sb + OFF_AH + c_d1, Ah + c_g1 + kc);
        cpa16(sb + OFF_AL + c_d1, Al + c_g1 + kc);
        cpa16(sb + OFF_BH + c_d1, Bh + c_g1 + kc);
        cpa16(sb + OFF_BL + c_d1, Bl + c_g1 + kc);
        cp_commit();
    }

    int stage = 0;
    int pstage = 2;
    for (int ch = 0; ch < 32; ch++) {
        if (ch + 1 < 32) cp_wait1(); else cp_wait0();
        __syncthreads();

        if (ch + 2 < 32) {
            uint32_t sb = sbase + pstage * K2_STG;
            int kc = (ch + 2) * 32;
            cpa16(sb + OFF_AH + c_d0, Ah + c_g0 + kc);
            cpa16(sb + OFF_AL + c_d0, Al + c_g0 + kc);
            cpa16(sb + OFF_BH + c_d0, Bh + c_g0 + kc);
            cpa16(sb + OFF_BL + c_d0, Bl + c_g0 + kc);
            cpa16(sb + OFF_AH + c_d1, Ah + c_g1 + kc);
            cpa16(sb + OFF_AL + c_d1, Al + c_g1 + kc);
            cpa16(sb + OFF_BH + c_d1, Bh + c_g1 + kc);
            cpa16(sb + OFF_BL + c_d1, Bl + c_g1 + kc);
            cp_commit();
        }

        uint32_t sb = sbase + stage * K2_STG;
#pragma unroll
        for (int ks = 0; ks < 2; ks++) {
            uint32_t bh[2][4], bl[2][4];
#pragma unroll
            for (int j = 0; j < 2; j++) {
                ldsm_x4(sb + OFF_BH + offB[j][ks], bh[j]);
                ldsm_x4(sb + OFF_BL + offB[j][ks], bl[j]);
            }
#pragma unroll
            for (int i = 0; i < 4; i++) {
                uint32_t ah[4], al[4];
                ldsm_x4(sb + OFF_AH + offA[i][ks], ah);
                ldsm_x4(sb + OFF_AL + offA[i][ks], al);
#pragma unroll
                for (int jn = 0; jn < 4; jn++) {
                    const int jj = jn >> 1;
                    const int ss = jn & 1;
                    mma_bf16(acc[i][jn], ah, bh[jj][ss], bh[jj][ss + 2]);
                    mma_bf16(acc[i][jn], ah, bl[jj][ss], bl[jj][ss + 2]);
                    mma_bf16(acc[i][jn], al, bh[jj][ss], bh[jj][ss + 2]);
                }
            }
        }
        stage  = (stage == 2) ? 0 : stage + 1;
        pstage = (pstage == 2) ? 0 : pstage + 1;
    }

    const int rowc = lid >> 2;
    const int colc = (lid & 3) * 2;
#pragma unroll
    for (int i = 0; i < 4; i++) {
        int m0 = mb + mw + i * 16 + rowc;
#pragma unroll
        for (int jn = 0; jn < 4; jn++) {
            int n0 = nb + nw + jn * 8 + colc;
            *(float2*)&g_gates[((size_t)m0 * NBO + kb) * GATES + n0] =
                make_float2(acc[i][jn][0], acc[i][jn][1]);
            *(float2*)&g_gates[((size_t)(m0 + 8) * NBO + kb) * GATES + n0] =
                make_float2(acc[i][jn][2], acc[i][jn][3]);
        }
    }
}

// =====================================================================
// K3: LSTM elementwise, float4-vectorized; also emits h_new bf16 hi/lo.
// =====================================================================
__global__ void __launch_bounds__(256) k3_lstm_ew(
    const float* __restrict__ cx, const float* __restrict__ b_ih,
    const float* __restrict__ b_hh, float* __restrict__ cx_out)
{
    size_t i4 = (size_t)blockIdx.x * blockDim.x + threadIdx.x;
    size_t bk = i4 >> 7;
    int kb = (int)(bk & 7);
    int d  = (int)(i4 & 127) * 4;
    const float* g  = &g_gates[bk * GATES];
    const float* bi = &b_ih[(size_t)kb * GATES];
    const float* bh = &b_hh[(size_t)kb * GATES];

    float4 gi = *(const float4*)&g[d];
    float4 gf = *(const float4*)&g[d + 512];
    float4 gg = *(const float4*)&g[d + 1024];
    float4 go = *(const float4*)&g[d + 1536];
    float4 bi_i = *(const float4*)&bi[d],        bh_i = *(const float4*)&bh[d];
    float4 bi_f = *(const float4*)&bi[d + 512],  bh_f = *(const float4*)&bh[d + 512];
    float4 bi_g = *(const float4*)&bi[d + 1024], bh_g = *(const float4*)&bh[d + 1024];
    float4 bi_o = *(const float4*)&bi[d + 1536], bh_o = *(const float4*)&bh[d + 1536];
    float4 cb = *(const float4*)&cx[bk * BSO + d];
    float m = g_mblk[bk];

    float hn[4], co[4];
    float giv[4] = {gi.x, gi.y, gi.z, gi.w};
    float gfv[4] = {gf.x, gf.y, gf.z, gf.w};
    float ggv[4] = {gg.x, gg.y, gg.z, gg.w};
    float gov[4] = {go.x, go.y, go.z, go.w};
    float biiv[4] = {bi_i.x, bi_i.y, bi_i.z, bi_i.w};
    float bhiv[4] = {bh_i.x, bh_i.y, bh_i.z, bh_i.w};
    float bifv[4] = {bi_f.x, bi_f.y, bi_f.z, bi_f.w};
    float bhfv[4] = {bh_f.x, bh_f.y, bh_f.z, bh_f.w};
    float bigv[4] = {bi_g.x, bi_g.y, bi_g.z, bi_g.w};
    float bhgv[4] = {bh_g.x, bh_g.y, bh_g.z, bh_g.w};
    float biov[4] = {bi_o.x, bi_o.y, bi_o.z, bi_o.w};
    float bhov[4] = {bh_o.x, bh_o.y, bh_o.z, bh_o.w};
    float cbv[4] = {cb.x, cb.y, cb.z, cb.w};
#pragma unroll
    for (int j = 0; j < 4; j++) {
        float ig = sigf(giv[j] + biiv[j] + bhiv[j]);
        float fg = sigf(gfv[j] + bifv[j] + bhfv[j]);
        float gt = tanhf(ggv[j] + bigv[j] + bhgv[j]);
        float og = sigf(gov[j] + biov[j] + bhov[j]);
        float cn = fg * cbv[j] + ig * gt;
        hn[j] = og * tanhf(cn);
        co[j] = m * cn + (1.0f - m) * cbv[j];
    }
    *(float4*)&g_hnew[bk * BSO + d]  = make_float4(hn[0], hn[1], hn[2], hn[3]);
    *(float4*)&cx_out[bk * BSO + d] = make_float4(co[0], co[1], co[2], co[3]);

    union { __nv_bfloat16 h[4]; uint2 u; } vh, vl;
#pragma unroll
    for (int j = 0; j < 4; j++) {
        __nv_bfloat16 hi = __float2bfloat16(hn[j]);
        vh.h[j] = hi;
        vl.h[j] = __float2bfloat16(hn[j] - __bfloat162float(hi));
    }
    size_t ho = ((size_t)kb * 1024 + (bk >> 3)) * 512 + d;
    *(uint2*)&g_h2hi[ho] = vh.u;
    *(uint2*)&g_h2lo[ho] = vl.u;
}

// =====================================================================
// K4M: q2/k2/v2 GEMMs on mma.sync bf16 (hi/lo 3 passes).
//   CTA tile M=64, N=64, K=512 in 16 chunks of 32; double buffer.
//   8 warps = 4m x 2n, warp tile 16x32.  grid (3, 16, 8) = 384.
// =====================================================================
#define K4_STG   16384
#define K4_SMEM  (2 * K4_STG)      /* 32768 */
#define K4_AH    0
#define K4_AL    4096
#define K4_BH    8192
#define K4_BL    12288

__global__ void __launch_bounds__(256) k4m_qkv()
{
    extern __shared__ char smem[];
    const int tid = threadIdx.x;
    const int wid = tid >> 5;
    const int lid = tid & 31;
    const uint32_t sbase = smem_u32(smem);
    const int mat = blockIdx.x;
    const int mb  = blockIdx.y * 64;
    const int kb  = blockIdx.z;

    const __nv_bfloat16* Ah = g_h2hi + ((size_t)kb * 1024 + mb) * 512;
    const __nv_bfloat16* Al = g_h2lo + ((size_t)kb * 1024 + mb) * 512;
    const __nv_bfloat16* Bh = g_wqhi + (size_t)(mat * 8 + kb) * 64 * 512;
    const __nv_bfloat16* Bl = g_wqlo + (size_t)(mat * 8 + kb) * 64 * 512;

    const int mw = (wid >> 1) * 16;
    const int nw = (wid & 1) * 32;
    const int g  = lid >> 3;
    const int r  = lid & 7;

    uint32_t offA[2], offB[2][2];
#pragma unroll
    for (int ks = 0; ks < 2; ks++) {
        int m = mw + (g & 1) * 8 + r;
        int k = ks * 16 + (g >> 1) * 8;
        offA[ks] = swz64((uint32_t)(m * 64 + k * 2));
    }
#pragma unroll
    for (int j = 0; j < 2; j++)
#pragma unroll
        for (int ks = 0; ks < 2; ks++) {
            int n = nw + j * 16 + (g & 1) * 8 + r;
            int k = ks * 16 + (g >> 1) * 8;
            offB[j][ks] = swz64((uint32_t)(n * 64 + k * 2));
        }

    float acc[4][4];
#pragma unroll
    for (int j = 0; j < 4; j++)
#pragma unroll
        for (int c = 0; c < 4; c++) acc[j][c] = 0.f;

    // cp.async mapping: rows 0..63 for A and B, 1 slot of 16B each
    const int a_row = tid >> 2;
    const int a_sl  = tid & 3;
    const uint32_t a_d = swz64((uint32_t)(a_row * 64 + a_sl * 16));
    const size_t  a_g = (size_t)a_row * 512 + a_sl * 8;

    {
        uint32_t sb = sbase;
        cpa16(sb + K4_AH + a_d, Ah + a_g);
        cpa16(sb + K4_AL + a_d, Al + a_g);
        cpa16(sb + K4_BH + a_d, Bh + a_g);
        cpa16(sb + K4_BL + a_d, Bl + a_g);
        cp_commit();
    }

    for (int ch = 0; ch < 16; ch++) {
        if (ch + 1 < 16) {
            uint32_t sb = sbase + ((ch + 1) & 1) * K4_STG;
            int kc = (ch + 1) * 32;
            cpa16(sb + K4_AH + a_d, Ah + a_g + kc);
            cpa16(sb + K4_AL + a_d, Al + a_g + kc);
            cpa16(sb + K4_BH + a_d, Bh + a_g + kc);
            cpa16(sb + K4_BL + a_d, Bl + a_g + kc);
            cp_commit();
            cp_wait1();
        } else {
            cp_wait0();
        }
        __syncthreads();

        uint32_t sb = sbase + (ch & 1) * K4_STG;
#pragma unroll
        for (int ks = 0; ks < 2; ks++) {
            uint32_t bh[2][4], bl[2][4];
#pragma unroll
            for (int j = 0; j < 2; j++) {
                ldsm_x4(sb + K4_BH + offB[j][ks], bh[j]);
                ldsm_x4(sb + K4_BL + offB[j][ks], bl[j]);
            }
            uint32_t ah[4], al[4];
            ldsm_x4(sb + K4_AH + offA[ks], ah);
            ldsm_x4(sb + K4_AL + offA[ks], al);
#pragma unroll
            for (int jn = 0; jn < 4; jn++) {
                const int jj = jn >> 1;
                const int ss = jn & 1;
                mma_bf16(acc[jn], ah, bh[jj][ss], bh[jj][ss + 2]);
                mma_bf16(acc[jn], ah, bl[jj][ss], bl[jj][ss + 2]);
                mma_bf16(acc[jn], al, bh[jj][ss], bh[jj][ss + 2]);
            }
        }
        __syncthreads();
    }

    float* dst = (mat == 0) ? g_q2 : (mat == 1) ? g_k2 : g_v2;
    const int rowc = lid >> 2;
    const int colc = (lid & 3) * 2;
    {
        int m0 = mb + mw + rowc;
#pragma unroll
        for (int jn = 0; jn < 4; jn++) {
            int n0 = nw + jn * 8 + colc;
            *(float2*)&dst[((size_t)m0 * NBO + kb) * DKQ + n0] =
                make_float2(acc[jn][0], acc[jn][1]);
            *(float2*)&dst[((size_t)(m0 + 8) * NBO + kb) * DKQ + n0] =
                make_float2(acc[jn][2], acc[jn][3]);
        }
    }
}

// =====================================================================
// K5: MHA attend + fc/gate + final hx_out combine.  FFMA2 accumulators.
// =====================================================================
__global__ void __launch_bounds__(256) k5_mha(
    const float* __restrict__ hx,
    const float* __restrict__ fcw, const float* __restrict__ fcb,
    const float* __restrict__ gw,  const float* __restrict__ gb,
    float* __restrict__ hx_out)
{
    __shared__ float sq2[NBO][DKQ];
    __shared__ float sk2[NBO][DKQ];
    __shared__ float sv2[NBO][DKQ];
    __shared__ float sat[NBO][NBO];
    __shared__ float so2[NBO][DKQ];

    const int tid = threadIdx.x;
    const size_t b = blockIdx.x;

    for (int i = tid; i < NBO * DKQ; i += 256) {
        ((float*)sq2)[i] = g_q2[b * NBO * DKQ + i];
        ((float*)sk2)[i] = g_k2[b * NBO * DKQ + i];
        ((float*)sv2)[i] = g_v2[b * NBO * DKQ + i];
    }
    __syncthreads();

    if (tid < 64) {
        int kq = tid >> 3, kj = tid & 7;
        float s = 0.f;
        for (int e = 0; e < DKQ; e++) s += sq2[kq][e] * sk2[kj][e];
        sat[kq][kj] = s * 0.125f;
    }
    __syncthreads();
    if (tid < NBO) {
        float mx = -1e30f;
        for (int j = 0; j < NBO; j++) mx = fmaxf(mx, sat[tid][j]);
        float den = 0.f;
        for (int j = 0; j < NBO; j++) { float e = expf(sat[tid][j] - mx); sat[tid][j] = e; den += e; }
        float inv = 1.0f / den;
        for (int j = 0; j < NBO; j++) sat[tid][j] *= inv;
    }
    __syncthreads();
    for (int i = tid; i < NBO * DKQ; i += 256) {
        int k = i >> 6, e = i & 63;
        float a = 0.f;
        for (int j = 0; j < NBO; j++) a += sat[k][j] * sv2[j][e];
        so2[k][e] = a;
    }
    __syncthreads();

    const int d0 = tid * 2;
    unsigned long long aof[NBO], agf[NBO];
#pragma unroll
    for (int k = 0; k < NBO; k++) { aof[k] = 0ULL; agf[k] = 0ULL; }

    for (int e = 0; e < DKQ; e++) {
        float2 fw  = *(const float2*)&fcw[(size_t)e * BSO + d0];
        float2 gwv = *(const float2*)&gw[(size_t)e * BSO + d0];
        unsigned long long fwp = pk2(fw.x, fw.y);
        unsigned long long gwp = pk2(gwv.x, gwv.y);
#pragma unroll
        for (int k = 0; k < NBO; k++) {
            float o = so2[k][e];
            unsigned long long oo = pk2(o, o);
            fma2(aof[k], oo, fwp);
            fma2(agf[k], oo, gwp);
        }
    }

    float fb0 = fcb[d0], fb1 = fcb[d0 + 1];
    float gb0 = gb[d0],  gb1 = gb[d0 + 1];
#pragma unroll
    for (int k = 0; k < NBO; k++) {
        float2 ao = upk2(aof[k]);
        float2 ag = upk2(agf[k]);
        float m = g_mblk[b * NBO + k];
        float hn0 = g_hnew[(b * NBO + k) * BSO + d0];
        float hn1 = g_hnew[(b * NBO + k) * BSO + d0 + 1];
        float v0 = hn0 + sigf(ag.x + gb0) * tanhf(ao.x + fb0);
        float v1 = hn1 + sigf(ag.y + gb1) * tanhf(ao.y + fb1);
        size_t idx = b * NHID + (size_t)k * BSO + d0;
        hx_out[idx]     = m * v0 + (1.0f - m) * hx[idx];
        hx_out[idx + 1] = m * v1 + (1.0f - m) * hx[idx + 1];
    }
}

// =====================================================================
extern "C" void kernel_launch(void* const* d_in, const int* in_sizes, int n_in,
                              void* d_out, int out_size) {
    const float* inp    = (const float*)d_in[0];
    const float* hx     = (const float*)d_in[1];
    const float* cx     = (const float*)d_in[2];
    const float* ia_wq  = (const float*)d_in[3];
    const float* ia_wk  = (const float*)d_in[4];
    const float* ia_wv  = (const float*)d_in[5];
    const float* ia_fcw = (const float*)d_in[6];
    const float* ia_fcb = (const float*)d_in[7];
    const float* mha_wq = (const float*)d_in[8];
    const float* mha_wk = (const float*)d_in[9];
    const float* mha_wv = (const float*)d_in[10];
    const float* mha_fcw= (const float*)d_in[11];
    const float* mha_fcb= (const float*)d_in[12];
    const float* mha_gw = (const float*)d_in[13];
    const float* mha_gb = (const float*)d_in[14];
    const float* w_ih   = (const float*)d_in[15];
    const float* w_hh   = (const float*)d_in[16];
    const float* b_ih   = (const float*)d_in[17];
    const float* b_hh   = (const float*)d_in[18];

    float* out   = (float*)d_out;
    const size_t N = (size_t)BSZ * NHID;
    float* out_hx   = out;
    float* out_cx   = out + N;
    float* out_mask = out + 2 * N;

    cudaFuncSetAttribute(k2m_gemm, cudaFuncAttributeMaxDynamicSharedMemorySize, K2_SMEM);
    cudaFuncSetAttribute(k4m_qkv, cudaFuncAttributeMaxDynamicSharedMemorySize, K4_SMEM);

    k_pre<<<PRE_BLOCKS, 256>>>(inp, hx, ia_wq, ia_wk, ia_wv, ia_fcw, ia_fcb,
                               w_ih, w_hh, mha_wq, mha_wk, mha_wv, out_mask);
    k2m_gemm<<<dim3(GATES / 128, BSZ / 128, NBO), 256, K2_SMEM>>>();
    k3_lstm_ew<<<(unsigned)(((size_t)BSZ * NBO * BSO / 4 + 255) / 256), 256>>>(cx, b_ih, b_hh, out_cx);
    k4m_qkv<<<dim3(3, BSZ / 64, NBO), 256, K4_SMEM>>>();
    k5_mha<<<BSZ, 256>>>(hx, mha_fcw, mha_fcb, mha_gw, mha_gb, out_hx);
}